// round 2
// baseline (speedup 1.0000x reference)
#include <cuda_runtime.h>

#define NN 100000
#define EE 1600000
#define HID_F 128
#define OUT_F 64

// ---------------- scratch (static device globals; no allocation) ----------------
__device__ __align__(128) int   g_outdeg[NN];
__device__ __align__(128) int   g_indeg[NN];
__device__ __align__(128) float g_c_src[NN];
__device__ __align__(128) float g_c_dst[NN];
__device__ __align__(128) int   g_rowptr[NN + 1];
__device__ __align__(128) int   g_cursor[NN];
__device__ __align__(128) int   g_csr_src[EE];
__device__ __align__(128) float g_h[(size_t)NN * HID_F];    // layer1 GEMM out
__device__ __align__(128) float g_h1s[(size_t)NN * HID_F];  // relu(agg)*c_src
__device__ __align__(128) float g_h2[(size_t)NN * OUT_F];   // layer2 GEMM out
__device__ __align__(128) float g_out_acc[OUT_F];

// ---------------- kernels ----------------

__global__ void k_zero() {
    int i = blockIdx.x * blockDim.x + threadIdx.x;
    int stride = gridDim.x * blockDim.x;
    for (int t = i; t < NN; t += stride) { g_outdeg[t] = 0; g_indeg[t] = 0; }
    if (i < OUT_F) g_out_acc[i] = 0.0f;
}

__global__ void k_degree(const int* __restrict__ src, const int* __restrict__ dst) {
    int i = blockIdx.x * blockDim.x + threadIdx.x;
    int stride = gridDim.x * blockDim.x;
    for (int e = i; e < EE; e += stride) {
        atomicAdd(&g_outdeg[src[e]], 1);
        atomicAdd(&g_indeg[dst[e]], 1);
    }
}

__global__ void k_coeff() {
    int i = blockIdx.x * blockDim.x + threadIdx.x;
    int stride = gridDim.x * blockDim.x;
    for (int t = i; t < NN; t += stride) {
        g_c_src[t] = rsqrtf((float)max(g_outdeg[t], 1));
        g_c_dst[t] = rsqrtf((float)max(g_indeg[t], 1));
    }
}

// exclusive prefix sum of g_indeg -> g_rowptr / g_cursor, single block of 1024
__global__ void k_scan() {
    __shared__ int wsum[32];
    __shared__ int carry_sh;
    int tid = threadIdx.x;
    int lane = tid & 31, wid = tid >> 5;
    if (tid == 0) carry_sh = 0;
    __syncthreads();
    for (int base = 0; base < NN; base += 1024) {
        int i = base + tid;
        int v = (i < NN) ? g_indeg[i] : 0;
        int x = v;
#pragma unroll
        for (int off = 1; off < 32; off <<= 1) {
            int y = __shfl_up_sync(0xffffffffu, x, off);
            if (lane >= off) x += y;
        }
        if (lane == 31) wsum[wid] = x;
        __syncthreads();
        if (wid == 0) {
            int s = wsum[lane];
#pragma unroll
            for (int off = 1; off < 32; off <<= 1) {
                int y = __shfl_up_sync(0xffffffffu, s, off);
                if (lane >= off) s += y;
            }
            wsum[lane] = s;
        }
        __syncthreads();
        int excl = x - v + ((wid == 0) ? 0 : wsum[wid - 1]);
        int carry = carry_sh;
        if (i < NN) { g_rowptr[i] = carry + excl; g_cursor[i] = carry + excl; }
        __syncthreads();
        if (tid == 1023) carry_sh = carry + wsum[31];
        __syncthreads();
    }
    if (tid == 0) g_rowptr[NN] = carry_sh;
}

__global__ void k_scatter(const int* __restrict__ src, const int* __restrict__ dst) {
    int i = blockIdx.x * blockDim.x + threadIdx.x;
    int stride = gridDim.x * blockDim.x;
    for (int e = i; e < EE; e += stride) {
        int p = atomicAdd(&g_cursor[dst[e]], 1);
        g_csr_src[p] = src[e];
    }
}

// C = (A * scale) @ W,  A: [NN,128], W: [128,NCOLS].
// FIRST: A=param feat, scale=c_src, C=g_h.  else: A=g_h1s, scale=1, C=g_h2.
template <int NCOLS, bool FIRST>
__global__ void __launch_bounds__(256)
k_gemm(const float* __restrict__ Aext, const float* __restrict__ W) {
    constexpr int BM = 64;
    constexpr int TN = NCOLS / 16;
    extern __shared__ float smem[];
    float* As = smem;               // BM x 132 (padded)
    float* Ws = smem + BM * 132;    // 128 x NCOLS
    const float* A = FIRST ? Aext : g_h1s;
    float* C = FIRST ? g_h : g_h2;

    int tid = threadIdx.x;
    int row0 = blockIdx.x * BM;

    for (int i = tid * 4; i < 128 * NCOLS; i += 256 * 4)
        *(float4*)&Ws[i] = *(const float4*)&W[i];

    for (int i = tid; i < BM * 32; i += 256) {
        int r = i >> 5, c4 = i & 31;
        int row = row0 + r;
        float4 v = make_float4(0.f, 0.f, 0.f, 0.f);
        float s = 1.0f;
        if (row < NN) {
            v = *(const float4*)&A[(size_t)row * 128 + c4 * 4];
            if (FIRST) s = g_c_src[row];
        }
        v.x *= s; v.y *= s; v.z *= s; v.w *= s;
        *(float4*)&As[r * 132 + c4 * 4] = v;
    }
    __syncthreads();

    int tx = tid & 15, ty = tid >> 4;
    float acc[4][TN];
#pragma unroll
    for (int i = 0; i < 4; i++)
#pragma unroll
        for (int j = 0; j < TN; j++) acc[i][j] = 0.0f;

#pragma unroll 4
    for (int k = 0; k < 128; k++) {
        float a[4];
#pragma unroll
        for (int i = 0; i < 4; i++) a[i] = As[(ty * 4 + i) * 132 + k];
        float w[TN];
#pragma unroll
        for (int j = 0; j < TN; j += 4) {
            float4 wv = *(float4*)&Ws[k * NCOLS + tx * TN + j];
            w[j] = wv.x; w[j + 1] = wv.y; w[j + 2] = wv.z; w[j + 3] = wv.w;
        }
#pragma unroll
        for (int i = 0; i < 4; i++)
#pragma unroll
            for (int j = 0; j < TN; j++) acc[i][j] = fmaf(a[i], w[j], acc[i][j]);
    }

#pragma unroll
    for (int i = 0; i < 4; i++) {
        int row = row0 + ty * 4 + i;
        if (row < NN) {
#pragma unroll
            for (int j = 0; j < TN; j += 4) {
                float4 o = make_float4(acc[i][j], acc[i][j + 1], acc[i][j + 2], acc[i][j + 3]);
                *(float4*)&C[(size_t)row * NCOLS + tx * TN + j] = o;
            }
        }
    }
}

// CSR aggregation of g_h + fused epilogue: h1s = relu(agg*c_dst + b1)*c_src
__global__ void k_spmm_relu(const float* __restrict__ b1) {
    int gw = (blockIdx.x * blockDim.x + threadIdx.x) >> 5;
    if (gw >= NN) return;
    int lane = threadIdx.x & 31;
    int beg = g_rowptr[gw], end = g_rowptr[gw + 1];
    float4 a0 = make_float4(0.f, 0.f, 0.f, 0.f);
    float4 a1 = make_float4(0.f, 0.f, 0.f, 0.f);
    int j = beg;
    for (; j + 1 < end; j += 2) {
        int s0 = g_csr_src[j];
        int s1 = g_csr_src[j + 1];
        float4 v0 = *(const float4*)(g_h + (size_t)s0 * 128 + lane * 4);
        float4 v1 = *(const float4*)(g_h + (size_t)s1 * 128 + lane * 4);
        a0.x += v0.x; a0.y += v0.y; a0.z += v0.z; a0.w += v0.w;
        a1.x += v1.x; a1.y += v1.y; a1.z += v1.z; a1.w += v1.w;
    }
    if (j < end) {
        int s = g_csr_src[j];
        float4 v = *(const float4*)(g_h + (size_t)s * 128 + lane * 4);
        a0.x += v.x; a0.y += v.y; a0.z += v.z; a0.w += v.w;
    }
    float cd = g_c_dst[gw], cs = g_c_src[gw];
    float4 bb = *(const float4*)(b1 + lane * 4);
    float4 o;
    o.x = fmaxf(fmaf(a0.x + a1.x, cd, bb.x), 0.0f) * cs;
    o.y = fmaxf(fmaf(a0.y + a1.y, cd, bb.y), 0.0f) * cs;
    o.z = fmaxf(fmaf(a0.z + a1.z, cd, bb.z), 0.0f) * cs;
    o.w = fmaxf(fmaf(a0.w + a1.w, cd, bb.w), 0.0f) * cs;
    *(float4*)(g_h1s + (size_t)gw * 128 + lane * 4) = o;
}

// out_acc[c] = sum_e c_dst[dst_e] * h2[src_e][c]   (replaces SpMM2 + weighted mean)
__global__ void k_edge_reduce(const int* __restrict__ src, const int* __restrict__ dst) {
    __shared__ float sh[OUT_F];
    int tid = threadIdx.x;
    if (tid < OUT_F) sh[tid] = 0.0f;
    __syncthreads();
    int lane = tid & 31;
    int gw = (blockIdx.x * blockDim.x + tid) >> 5;
    int nw = (gridDim.x * blockDim.x) >> 5;
    float ax = 0.0f, ay = 0.0f;
    for (int e = gw; e < EE; e += nw) {
        int s = src[e];
        int d = dst[e];
        float cd = g_c_dst[d];
        float2 v = *(const float2*)(g_h2 + (size_t)s * OUT_F + lane * 2);
        ax = fmaf(cd, v.x, ax);
        ay = fmaf(cd, v.y, ay);
    }
    atomicAdd(&sh[lane * 2], ax);
    atomicAdd(&sh[lane * 2 + 1], ay);
    __syncthreads();
    if (tid < OUT_F) atomicAdd(&g_out_acc[tid], sh[tid]);
}

__global__ void k_final(const float* __restrict__ b2, float* __restrict__ out) {
    int i = threadIdx.x;
    if (i < OUT_F) out[i] = g_out_acc[i] * (1.0f / (float)NN) + b2[i];
}

// ---------------- launch ----------------
extern "C" void kernel_launch(void* const* d_in, const int* in_sizes, int n_in,
                              void* d_out, int out_size) {
    const float* feat = (const float*)d_in[0];
    const int*   src  = (const int*)d_in[1];
    const int*   dst  = (const int*)d_in[2];
    const float* W1   = (const float*)d_in[3];
    const float* b1   = (const float*)d_in[4];
    const float* W2   = (const float*)d_in[5];
    const float* b2   = (const float*)d_in[6];
    float* out = (float*)d_out;

    (void)in_sizes; (void)n_in; (void)out_size;

    k_zero<<<256, 256>>>();
    k_degree<<<2048, 256>>>(src, dst);
    k_coeff<<<(NN + 255) / 256, 256>>>();
    k_scan<<<1, 1024>>>();
    k_scatter<<<2048, 256>>>(src, dst);

    size_t smem1 = (size_t)(64 * 132 + 128 * 128) * sizeof(float);  // 99328 B
    size_t smem2 = (size_t)(64 * 132 + 128 * 64) * sizeof(float);   // 66560 B
    cudaFuncSetAttribute(k_gemm<128, true>, cudaFuncAttributeMaxDynamicSharedMemorySize, (int)smem1);
    cudaFuncSetAttribute(k_gemm<64, false>, cudaFuncAttributeMaxDynamicSharedMemorySize, (int)smem2);

    k_gemm<128, true><<<(NN + 63) / 64, 256, smem1>>>(feat, W1);
    k_spmm_relu<<<(NN * 32 + 255) / 256, 256>>>(b1);
    k_gemm<64, false><<<(NN + 63) / 64, 256, smem2>>>(nullptr, W2);
    k_edge_reduce<<<1776, 256>>>(src, dst);
    k_final<<<1, 64>>>(b2, out);
}

// round 3
// speedup vs baseline: 1.0046x; 1.0046x over previous
#include <cuda_runtime.h>

#define NN 100000
#define EE 1600000
#define HID_F 128
#define OUT_F 64

// ---------------- scratch (static device globals; no allocation) ----------------
__device__ __align__(128) int   g_outdeg[NN];
__device__ __align__(128) int   g_indeg[NN];
__device__ __align__(128) float g_c_src[NN];
__device__ __align__(128) float g_c_dst[NN];
__device__ __align__(128) int   g_rowptr[NN + 1];
__device__ __align__(128) int   g_cursor[NN];
__device__ __align__(128) int   g_csr_src[EE];
__device__ __align__(128) float g_h[(size_t)NN * HID_F];    // layer1 GEMM out
__device__ __align__(128) float g_h1s[(size_t)NN * HID_F];  // relu(agg)*c_src
__device__ __align__(128) float g_h2[(size_t)NN * OUT_F];   // layer2 GEMM out
__device__ __align__(128) float g_out_acc[OUT_F];

// ---------------- kernels ----------------

__global__ void k_zero() {
    int i = blockIdx.x * blockDim.x + threadIdx.x;
    int stride = gridDim.x * blockDim.x;
    for (int t = i; t < NN; t += stride) { g_outdeg[t] = 0; g_indeg[t] = 0; }
    if (i < OUT_F) g_out_acc[i] = 0.0f;
}

__global__ void k_degree(const int* __restrict__ src, const int* __restrict__ dst) {
    int i = blockIdx.x * blockDim.x + threadIdx.x;
    int stride = gridDim.x * blockDim.x;
    for (int e = i; e < EE; e += stride) {
        atomicAdd(&g_outdeg[src[e]], 1);
        atomicAdd(&g_indeg[dst[e]], 1);
    }
}

__global__ void k_coeff() {
    int i = blockIdx.x * blockDim.x + threadIdx.x;
    int stride = gridDim.x * blockDim.x;
    for (int t = i; t < NN; t += stride) {
        g_c_src[t] = rsqrtf((float)max(g_outdeg[t], 1));
        g_c_dst[t] = rsqrtf((float)max(g_indeg[t], 1));
    }
}

// exclusive prefix sum of g_indeg -> g_rowptr / g_cursor, single block of 1024
__global__ void k_scan() {
    __shared__ int wsum[32];
    __shared__ int carry_sh;
    int tid = threadIdx.x;
    int lane = tid & 31, wid = tid >> 5;
    if (tid == 0) carry_sh = 0;
    __syncthreads();
    for (int base = 0; base < NN; base += 1024) {
        int i = base + tid;
        int v = (i < NN) ? g_indeg[i] : 0;
        int x = v;
#pragma unroll
        for (int off = 1; off < 32; off <<= 1) {
            int y = __shfl_up_sync(0xffffffffu, x, off);
            if (lane >= off) x += y;
        }
        if (lane == 31) wsum[wid] = x;
        __syncthreads();
        if (wid == 0) {
            int s = wsum[lane];
#pragma unroll
            for (int off = 1; off < 32; off <<= 1) {
                int y = __shfl_up_sync(0xffffffffu, s, off);
                if (lane >= off) s += y;
            }
            wsum[lane] = s;
        }
        __syncthreads();
        int excl = x - v + ((wid == 0) ? 0 : wsum[wid - 1]);
        int carry = carry_sh;
        if (i < NN) { g_rowptr[i] = carry + excl; g_cursor[i] = carry + excl; }
        __syncthreads();
        if (tid == 1023) carry_sh = carry + wsum[31];
        __syncthreads();
    }
    if (tid == 0) g_rowptr[NN] = carry_sh;
}

__global__ void k_scatter(const int* __restrict__ src, const int* __restrict__ dst) {
    int i = blockIdx.x * blockDim.x + threadIdx.x;
    int stride = gridDim.x * blockDim.x;
    for (int e = i; e < EE; e += stride) {
        int p = atomicAdd(&g_cursor[dst[e]], 1);
        g_csr_src[p] = src[e];
    }
}

// C = (A * scale) @ W,  A: [NN,128], W: [128,NCOLS].
// FIRST: A=param feat, scale=c_src, C=g_h.  else: A=g_h1s, scale=1, C=g_h2.
template <int NCOLS, bool FIRST>
__global__ void __launch_bounds__(256)
k_gemm(const float* __restrict__ Aext, const float* __restrict__ W) {
    constexpr int BM = 64;
    constexpr int TN = NCOLS / 16;
    extern __shared__ float smem[];
    float* As = smem;               // BM x 132 (padded)
    float* Ws = smem + BM * 132;    // 128 x NCOLS
    const float* A = FIRST ? Aext : g_h1s;
    float* C = FIRST ? g_h : g_h2;

    int tid = threadIdx.x;
    int row0 = blockIdx.x * BM;

    for (int i = tid * 4; i < 128 * NCOLS; i += 256 * 4)
        *(float4*)&Ws[i] = *(const float4*)&W[i];

    for (int i = tid; i < BM * 32; i += 256) {
        int r = i >> 5, c4 = i & 31;
        int row = row0 + r;
        float4 v = make_float4(0.f, 0.f, 0.f, 0.f);
        float s = 1.0f;
        if (row < NN) {
            v = *(const float4*)&A[(size_t)row * 128 + c4 * 4];
            if (FIRST) s = g_c_src[row];
        }
        v.x *= s; v.y *= s; v.z *= s; v.w *= s;
        *(float4*)&As[r * 132 + c4 * 4] = v;
    }
    __syncthreads();

    int tx = tid & 15, ty = tid >> 4;
    float acc[4][TN];
#pragma unroll
    for (int i = 0; i < 4; i++)
#pragma unroll
        for (int j = 0; j < TN; j++) acc[i][j] = 0.0f;

#pragma unroll 4
    for (int k = 0; k < 128; k++) {
        float a[4];
#pragma unroll
        for (int i = 0; i < 4; i++) a[i] = As[(ty * 4 + i) * 132 + k];
        float w[TN];
#pragma unroll
        for (int j = 0; j < TN; j += 4) {
            float4 wv = *(float4*)&Ws[k * NCOLS + tx * TN + j];
            w[j] = wv.x; w[j + 1] = wv.y; w[j + 2] = wv.z; w[j + 3] = wv.w;
        }
#pragma unroll
        for (int i = 0; i < 4; i++)
#pragma unroll
            for (int j = 0; j < TN; j++) acc[i][j] = fmaf(a[i], w[j], acc[i][j]);
    }

#pragma unroll
    for (int i = 0; i < 4; i++) {
        int row = row0 + ty * 4 + i;
        if (row < NN) {
#pragma unroll
            for (int j = 0; j < TN; j += 4) {
                float4 o = make_float4(acc[i][j], acc[i][j + 1], acc[i][j + 2], acc[i][j + 3]);
                *(float4*)&C[(size_t)row * NCOLS + tx * TN + j] = o;
            }
        }
    }
}

// CSR aggregation of g_h + fused epilogue: h1s = relu(agg*c_dst + b1)*c_src
__global__ void k_spmm_relu(const float* __restrict__ b1) {
    int gw = (blockIdx.x * blockDim.x + threadIdx.x) >> 5;
    if (gw >= NN) return;
    int lane = threadIdx.x & 31;
    int beg = g_rowptr[gw], end = g_rowptr[gw + 1];
    float4 a0 = make_float4(0.f, 0.f, 0.f, 0.f);
    float4 a1 = make_float4(0.f, 0.f, 0.f, 0.f);
    int j = beg;
    for (; j + 1 < end; j += 2) {
        int s0 = g_csr_src[j];
        int s1 = g_csr_src[j + 1];
        float4 v0 = *(const float4*)(g_h + (size_t)s0 * 128 + lane * 4);
        float4 v1 = *(const float4*)(g_h + (size_t)s1 * 128 + lane * 4);
        a0.x += v0.x; a0.y += v0.y; a0.z += v0.z; a0.w += v0.w;
        a1.x += v1.x; a1.y += v1.y; a1.z += v1.z; a1.w += v1.w;
    }
    if (j < end) {
        int s = g_csr_src[j];
        float4 v = *(const float4*)(g_h + (size_t)s * 128 + lane * 4);
        a0.x += v.x; a0.y += v.y; a0.z += v.z; a0.w += v.w;
    }
    float cd = g_c_dst[gw], cs = g_c_src[gw];
    float4 bb = *(const float4*)(b1 + lane * 4);
    float4 o;
    o.x = fmaxf(fmaf(a0.x + a1.x, cd, bb.x), 0.0f) * cs;
    o.y = fmaxf(fmaf(a0.y + a1.y, cd, bb.y), 0.0f) * cs;
    o.z = fmaxf(fmaf(a0.z + a1.z, cd, bb.z), 0.0f) * cs;
    o.w = fmaxf(fmaf(a0.w + a1.w, cd, bb.w), 0.0f) * cs;
    *(float4*)(g_h1s + (size_t)gw * 128 + lane * 4) = o;
}

// out_acc[c] = sum_e c_dst[dst_e] * h2[src_e][c]   (replaces SpMM2 + weighted mean)
__global__ void k_edge_reduce(const int* __restrict__ src, const int* __restrict__ dst) {
    __shared__ float sh[OUT_F];
    int tid = threadIdx.x;
    if (tid < OUT_F) sh[tid] = 0.0f;
    __syncthreads();
    int lane = tid & 31;
    int gw = (blockIdx.x * blockDim.x + tid) >> 5;
    int nw = (gridDim.x * blockDim.x) >> 5;
    float ax = 0.0f, ay = 0.0f;
    for (int e = gw; e < EE; e += nw) {
        int s = src[e];
        int d = dst[e];
        float cd = g_c_dst[d];
        float2 v = *(const float2*)(g_h2 + (size_t)s * OUT_F + lane * 2);
        ax = fmaf(cd, v.x, ax);
        ay = fmaf(cd, v.y, ay);
    }
    atomicAdd(&sh[lane * 2], ax);
    atomicAdd(&sh[lane * 2 + 1], ay);
    __syncthreads();
    if (tid < OUT_F) atomicAdd(&g_out_acc[tid], sh[tid]);
}

__global__ void k_final(const float* __restrict__ b2, float* __restrict__ out) {
    int i = threadIdx.x;
    if (i < OUT_F) out[i] = g_out_acc[i] * (1.0f / (float)NN) + b2[i];
}

// ---------------- launch ----------------
extern "C" void kernel_launch(void* const* d_in, const int* in_sizes, int n_in,
                              void* d_out, int out_size) {
    const float* feat = (const float*)d_in[0];
    const int*   src  = (const int*)d_in[1];
    const int*   dst  = (const int*)d_in[2];
    const float* W1   = (const float*)d_in[3];
    const float* b1   = (const float*)d_in[4];
    const float* W2   = (const float*)d_in[5];
    const float* b2   = (const float*)d_in[6];
    float* out = (float*)d_out;

    (void)in_sizes; (void)n_in; (void)out_size;

    k_zero<<<256, 256>>>();
    k_degree<<<2048, 256>>>(src, dst);
    k_coeff<<<(NN + 255) / 256, 256>>>();
    k_scan<<<1, 1024>>>();
    k_scatter<<<2048, 256>>>(src, dst);

    size_t smem1 = (size_t)(64 * 132 + 128 * 128) * sizeof(float);  // 99328 B
    size_t smem2 = (size_t)(64 * 132 + 128 * 64) * sizeof(float);   // 66560 B
    cudaFuncSetAttribute(k_gemm<128, true>, cudaFuncAttributeMaxDynamicSharedMemorySize, (int)smem1);
    cudaFuncSetAttribute(k_gemm<64, false>, cudaFuncAttributeMaxDynamicSharedMemorySize, (int)smem2);

    k_gemm<128, true><<<(NN + 63) / 64, 256, smem1>>>(feat, W1);
    k_spmm_relu<<<(NN * 32 + 255) / 256, 256>>>(b1);
    k_gemm<64, false><<<(NN + 63) / 64, 256, smem2>>>(nullptr, W2);
    k_edge_reduce<<<1776, 256>>>(src, dst);
    k_final<<<1, 64>>>(b2, out);
}

// round 4
// speedup vs baseline: 1.4966x; 1.4897x over previous
#include <cuda_runtime.h>

#define NN 100000
#define EE 1600000
#define HID_F 128
#define OUT_F 64
#define NB_SCAN 98   // ceil(NN/1024)

// ---------------- scratch (static device globals; no allocation) ----------------
__device__ __align__(128) int   g_outdeg[NN];
__device__ __align__(128) int   g_indeg[NN];
__device__ __align__(128) float g_c_src[NN];
__device__ __align__(128) float g_c_dst[NN];
__device__ __align__(128) int   g_rowptr[NN + 1];
__device__ __align__(128) int   g_cursor[NN];
__device__ __align__(128) int   g_csr_src[EE];
__device__ __align__(128) float g_w[NN];                    // w[s] = sum_{e:src=s} c_dst[dst_e]
__device__ __align__(128) float g_h[(size_t)NN * HID_F];    // layer1 GEMM out
__device__ __align__(128) float g_vacc[HID_F];              // sum_s w[s]*h1s[s]
__device__ __align__(128) int   g_bsum[NB_SCAN];
__device__ __align__(128) int   g_boff[NB_SCAN];

// ---------------- kernels ----------------

__global__ void k_zero() {
    int i = blockIdx.x * blockDim.x + threadIdx.x;
    int stride = gridDim.x * blockDim.x;
    for (int t = i; t < NN; t += stride) {
        g_outdeg[t] = 0; g_indeg[t] = 0; g_w[t] = 0.0f;
    }
    if (i < HID_F) g_vacc[i] = 0.0f;
}

__global__ void k_degree(const int* __restrict__ src, const int* __restrict__ dst) {
    int i = blockIdx.x * blockDim.x + threadIdx.x;
    int stride = gridDim.x * blockDim.x;
    for (int e = i; e < EE; e += stride) {
        atomicAdd(&g_outdeg[src[e]], 1);
        atomicAdd(&g_indeg[dst[e]], 1);
    }
}

// Per-block exclusive scan of g_indeg (local) + block totals; also computes coeffs.
__global__ void __launch_bounds__(1024) k_scan1() {
    __shared__ int wsum[32];
    int tid = threadIdx.x;
    int lane = tid & 31, wid = tid >> 5;
    int i = blockIdx.x * 1024 + tid;
    int v = (i < NN) ? g_indeg[i] : 0;

    // fused coeff computation (independent of scan)
    if (i < NN) {
        g_c_src[i] = rsqrtf((float)max(g_outdeg[i], 1));
        g_c_dst[i] = rsqrtf((float)max(v, 1));
    }

    int x = v;
#pragma unroll
    for (int off = 1; off < 32; off <<= 1) {
        int y = __shfl_up_sync(0xffffffffu, x, off);
        if (lane >= off) x += y;
    }
    if (lane == 31) wsum[wid] = x;
    __syncthreads();
    if (wid == 0) {
        int s = wsum[lane];
#pragma unroll
        for (int off = 1; off < 32; off <<= 1) {
            int y = __shfl_up_sync(0xffffffffu, s, off);
            if (lane >= off) s += y;
        }
        wsum[lane] = s;
    }
    __syncthreads();
    int excl = x - v + ((wid == 0) ? 0 : wsum[wid - 1]);
    if (i < NN) g_rowptr[i] = excl;   // local exclusive; offset added in scan3
    if (tid == 0) g_bsum[blockIdx.x] = wsum[31];
}

// Exclusive scan of the 98 block sums (single warp, 4 rounds with carry).
__global__ void k_scan2() {
    int lane = threadIdx.x;
    int carry = 0;
#pragma unroll
    for (int c = 0; c < (NB_SCAN + 31) / 32; c++) {
        int idx = c * 32 + lane;
        int v = (idx < NB_SCAN) ? g_bsum[idx] : 0;
        int x = v;
#pragma unroll
        for (int off = 1; off < 32; off <<= 1) {
            int y = __shfl_up_sync(0xffffffffu, x, off);
            if (lane >= off) x += y;
        }
        if (idx < NB_SCAN) g_boff[idx] = carry + x - v;
        carry += __shfl_sync(0xffffffffu, x, 31);
    }
}

// Add block offsets; init cursor; rowptr[NN] = EE (total in-degree is always E).
__global__ void k_scan3() {
    int i = blockIdx.x * blockDim.x + threadIdx.x;
    if (i < NN) {
        int rp = g_rowptr[i] + g_boff[i >> 10];
        g_rowptr[i] = rp;
        g_cursor[i] = rp;
    }
    if (i == 0) g_rowptr[NN] = EE;
}

// CSR scatter (by dst) fused with w[s] accumulation.
__global__ void k_scatter_wsum(const int* __restrict__ src, const int* __restrict__ dst) {
    int i = blockIdx.x * blockDim.x + threadIdx.x;
    int stride = gridDim.x * blockDim.x;
    for (int e = i; e < EE; e += stride) {
        int s = src[e];
        int d = dst[e];
        int p = atomicAdd(&g_cursor[d], 1);
        g_csr_src[p] = s;
        atomicAdd(&g_w[s], g_c_dst[d]);
    }
}

// g_h = (feat * c_src) @ W1   [NN,128] x [128,128]
__global__ void __launch_bounds__(256)
k_gemm1(const float* __restrict__ A, const float* __restrict__ W) {
    constexpr int BM = 64;
    constexpr int NCOLS = 128;
    constexpr int TN = 8;
    extern __shared__ float smem[];
    float* As = smem;               // BM x 132 (padded)
    float* Ws = smem + BM * 132;    // 128 x 128

    int tid = threadIdx.x;
    int row0 = blockIdx.x * BM;

    for (int i = tid * 4; i < 128 * NCOLS; i += 256 * 4)
        *(float4*)&Ws[i] = *(const float4*)&W[i];

    for (int i = tid; i < BM * 32; i += 256) {
        int r = i >> 5, c4 = i & 31;
        int row = row0 + r;
        float4 v = make_float4(0.f, 0.f, 0.f, 0.f);
        float s = 1.0f;
        if (row < NN) {
            v = *(const float4*)&A[(size_t)row * 128 + c4 * 4];
            s = g_c_src[row];
        }
        v.x *= s; v.y *= s; v.z *= s; v.w *= s;
        *(float4*)&As[r * 132 + c4 * 4] = v;
    }
    __syncthreads();

    int tx = tid & 15, ty = tid >> 4;
    float acc[4][TN];
#pragma unroll
    for (int i = 0; i < 4; i++)
#pragma unroll
        for (int j = 0; j < TN; j++) acc[i][j] = 0.0f;

#pragma unroll 4
    for (int k = 0; k < 128; k++) {
        float a[4];
#pragma unroll
        for (int i = 0; i < 4; i++) a[i] = As[(ty * 4 + i) * 132 + k];
        float w[TN];
#pragma unroll
        for (int j = 0; j < TN; j += 4) {
            float4 wv = *(float4*)&Ws[k * NCOLS + tx * TN + j];
            w[j] = wv.x; w[j + 1] = wv.y; w[j + 2] = wv.z; w[j + 3] = wv.w;
        }
#pragma unroll
        for (int i = 0; i < 4; i++)
#pragma unroll
            for (int j = 0; j < TN; j++) acc[i][j] = fmaf(a[i], w[j], acc[i][j]);
    }

#pragma unroll
    for (int i = 0; i < 4; i++) {
        int row = row0 + ty * 4 + i;
        if (row < NN) {
#pragma unroll
            for (int j = 0; j < TN; j += 4) {
                float4 o = make_float4(acc[i][j], acc[i][j + 1], acc[i][j + 2], acc[i][j + 3]);
                *(float4*)&g_h[(size_t)row * NCOLS + tx * TN + j] = o;
            }
        }
    }
}

// CSR aggregation of g_h + fused epilogue + fused weighted reduction:
//   o = relu(agg*c_dst + b1)*c_src ;  g_vacc += w[node]*o  (block-level reduce).
// Warp per node, 8 warps/block. No per-node output stored.
__global__ void __launch_bounds__(256) k_spmm_vacc(const float* __restrict__ b1) {
    __shared__ float sv[8][HID_F];
    int tid = threadIdx.x;
    int lane = tid & 31, wid = tid >> 5;
    int gw = blockIdx.x * 8 + wid;
    bool valid = (gw < NN);

    float4 o = make_float4(0.f, 0.f, 0.f, 0.f);
    if (valid) {
        int beg = g_rowptr[gw], end = g_rowptr[gw + 1];
        float4 a0 = make_float4(0.f, 0.f, 0.f, 0.f);
        float4 a1 = make_float4(0.f, 0.f, 0.f, 0.f);
        int j = beg;
        for (; j + 1 < end; j += 2) {
            int s0 = g_csr_src[j];
            int s1 = g_csr_src[j + 1];
            float4 v0 = *(const float4*)(g_h + (size_t)s0 * 128 + lane * 4);
            float4 v1 = *(const float4*)(g_h + (size_t)s1 * 128 + lane * 4);
            a0.x += v0.x; a0.y += v0.y; a0.z += v0.z; a0.w += v0.w;
            a1.x += v1.x; a1.y += v1.y; a1.z += v1.z; a1.w += v1.w;
        }
        if (j < end) {
            int s = g_csr_src[j];
            float4 v = *(const float4*)(g_h + (size_t)s * 128 + lane * 4);
            a0.x += v.x; a0.y += v.y; a0.z += v.z; a0.w += v.w;
        }
        float cd = g_c_dst[gw], cs = g_c_src[gw];
        float wn = g_w[gw] * cs;   // fold c_src and node weight together
        float4 bb = *(const float4*)(b1 + lane * 4);
        o.x = fmaxf(fmaf(a0.x + a1.x, cd, bb.x), 0.0f) * wn;
        o.y = fmaxf(fmaf(a0.y + a1.y, cd, bb.y), 0.0f) * wn;
        o.z = fmaxf(fmaf(a0.z + a1.z, cd, bb.z), 0.0f) * wn;
        o.w = fmaxf(fmaf(a0.w + a1.w, cd, bb.w), 0.0f) * wn;
    }
    *(float4*)&sv[wid][lane * 4] = o;
    __syncthreads();
    if (tid < HID_F) {
        float s = 0.0f;
#pragma unroll
        for (int w = 0; w < 8; w++) s += sv[w][tid];
        atomicAdd(&g_vacc[tid], s);
    }
}

// out = (g_vacc @ W2) / N + b2   -> [1, 64]
__global__ void k_final(const float* __restrict__ W2, const float* __restrict__ b2,
                        float* __restrict__ out) {
    __shared__ float v[HID_F];
    int tid = threadIdx.x;
    if (tid < HID_F) v[tid] = g_vacc[tid];
    __syncthreads();
    if (tid < OUT_F) {
        float s = 0.0f;
#pragma unroll 8
        for (int k = 0; k < HID_F; k++) s = fmaf(v[k], W2[k * OUT_F + tid], s);
        out[tid] = s * (1.0f / (float)NN) + b2[tid];
    }
}

// ---------------- launch ----------------
extern "C" void kernel_launch(void* const* d_in, const int* in_sizes, int n_in,
                              void* d_out, int out_size) {
    const float* feat = (const float*)d_in[0];
    const int*   src  = (const int*)d_in[1];
    const int*   dst  = (const int*)d_in[2];
    const float* W1   = (const float*)d_in[3];
    const float* b1   = (const float*)d_in[4];
    const float* W2   = (const float*)d_in[5];
    const float* b2   = (const float*)d_in[6];
    float* out = (float*)d_out;

    (void)in_sizes; (void)n_in; (void)out_size;

    k_zero<<<256, 256>>>();
    k_degree<<<2048, 256>>>(src, dst);
    k_scan1<<<NB_SCAN, 1024>>>();
    k_scan2<<<1, 32>>>();
    k_scan3<<<(NN + 255) / 256, 256>>>();
    k_scatter_wsum<<<2048, 256>>>(src, dst);

    size_t smem1 = (size_t)(64 * 132 + 128 * 128) * sizeof(float);  // 99328 B
    cudaFuncSetAttribute(k_gemm1, cudaFuncAttributeMaxDynamicSharedMemorySize, (int)smem1);
    k_gemm1<<<(NN + 63) / 64, 256, smem1>>>(feat, W1);

    k_spmm_vacc<<<(NN + 7) / 8, 256>>>(b1);
    k_final<<<1, 128>>>(W2, b2, out);
}

// round 6
// speedup vs baseline: 1.8509x; 1.2368x over previous
#include <cuda_runtime.h>
#include <cuda_bf16.h>
#include <cstdint>

#define NN 100000
#define EE 1600000
#define HID_F 128
#define OUT_F 64
#define NB_SCAN 98   // ceil(NN/1024)

// ---------------- scratch (static device globals; no allocation) ----------------
__device__ __align__(128) int   g_outdeg[NN];
__device__ __align__(128) int   g_indeg[NN];
__device__ __align__(128) float g_c_src[NN];
__device__ __align__(128) float g_c_dst[NN];
__device__ __align__(128) int   g_rowptr[NN + 1];
__device__ __align__(128) int   g_cursor[NN];
__device__ __align__(128) int   g_csr_src[EE];
__device__ __align__(128) float g_w[NN];                    // w[s] = sum_{e:src=s} c_dst[dst_e]
__device__ __align__(128) float g_h[(size_t)NN * HID_F];    // layer1 GEMM out
__device__ __align__(128) float g_vacc[HID_F];              // sum_s w[s]*relu(...)[s]
__device__ __align__(128) int   g_bsum[NB_SCAN];

// ---------------- helpers ----------------
__device__ __forceinline__ uint32_t smem_u32(const void* p) {
    uint32_t a;
    asm("{ .reg .u64 t; cvta.to.shared.u64 t, %1; cvt.u32.u64 %0, t; }" : "=r"(a) : "l"(p));
    return a;
}

#define LDSM_X4(r0, r1, r2, r3, addr) \
    asm volatile("ldmatrix.sync.aligned.m8n8.x4.shared.b16 {%0,%1,%2,%3}, [%4];" \
                 : "=r"(r0), "=r"(r1), "=r"(r2), "=r"(r3) : "r"(addr))

#define LDSM_X4_T(r0, r1, r2, r3, addr) \
    asm volatile("ldmatrix.sync.aligned.m8n8.x4.trans.shared.b16 {%0,%1,%2,%3}, [%4];" \
                 : "=r"(r0), "=r"(r1), "=r"(r2), "=r"(r3) : "r"(addr))

#define MMA_BF16(d, a0, a1, a2, a3, b0, b1) \
    asm volatile("mma.sync.aligned.m16n8k16.row.col.f32.bf16.bf16.f32 " \
                 "{%0,%1,%2,%3}, {%4,%5,%6,%7}, {%8,%9}, {%0,%1,%2,%3};" \
                 : "+f"((d)[0]), "+f"((d)[1]), "+f"((d)[2]), "+f"((d)[3]) \
                 : "r"(a0), "r"(a1), "r"(a2), "r"(a3), "r"(b0), "r"(b1))

__device__ __forceinline__ uint32_t pack_bf2(float f0, float f1) {
    __nv_bfloat162 t = __floats2bfloat162_rn(f0, f1);  // .x = f0 in low 16 bits
    return *reinterpret_cast<uint32_t*>(&t);
}

// ---------------- kernels ----------------

__global__ void k_zero() {
    int i = blockIdx.x * blockDim.x + threadIdx.x;
    int stride = gridDim.x * blockDim.x;
    for (int t = i; t < NN; t += stride) {
        g_outdeg[t] = 0; g_indeg[t] = 0; g_w[t] = 0.0f;
    }
    if (i < HID_F) g_vacc[i] = 0.0f;
}

__global__ void k_degree(const int* __restrict__ src, const int* __restrict__ dst) {
    int i = blockIdx.x * blockDim.x + threadIdx.x;
    int stride = gridDim.x * blockDim.x;
    for (int e = i; e < EE; e += stride) {
        atomicAdd(&g_outdeg[src[e]], 1);
        atomicAdd(&g_indeg[dst[e]], 1);
    }
}

// Per-block exclusive scan of g_indeg (local) + block totals; fused coeff computation.
__global__ void __launch_bounds__(1024) k_scan1() {
    __shared__ int wsum[32];
    int tid = threadIdx.x;
    int lane = tid & 31, wid = tid >> 5;
    int i = blockIdx.x * 1024 + tid;
    int v = (i < NN) ? g_indeg[i] : 0;

    if (i < NN) {
        g_c_src[i] = rsqrtf((float)max(g_outdeg[i], 1));
        g_c_dst[i] = rsqrtf((float)max(v, 1));
    }

    int x = v;
#pragma unroll
    for (int off = 1; off < 32; off <<= 1) {
        int y = __shfl_up_sync(0xffffffffu, x, off);
        if (lane >= off) x += y;
    }
    if (lane == 31) wsum[wid] = x;
    __syncthreads();
    if (wid == 0) {
        int s = wsum[lane];
#pragma unroll
        for (int off = 1; off < 32; off <<= 1) {
            int y = __shfl_up_sync(0xffffffffu, s, off);
            if (lane >= off) s += y;
        }
        wsum[lane] = s;
    }
    __syncthreads();
    int excl = x - v + ((wid == 0) ? 0 : wsum[wid - 1]);
    if (i < NN) g_rowptr[i] = excl;   // local exclusive; global offset added in scan3
    if (tid == 0) g_bsum[blockIdx.x] = wsum[31];
}

// Add block offsets (each block prefix-sums the 98 block sums itself); init cursor.
__global__ void __launch_bounds__(1024) k_scan3() {
    __shared__ int s_off;
    int tid = threadIdx.x;
    int b = blockIdx.x;
    if (tid < 32) {
        int off = 0;
#pragma unroll
        for (int c = 0; c < (NB_SCAN + 31) / 32; c++) {
            int idx = c * 32 + tid;
            if (idx < b) off += g_bsum[idx];
        }
#pragma unroll
        for (int o = 16; o > 0; o >>= 1) off += __shfl_down_sync(0xffffffffu, off, o);
        if (tid == 0) s_off = off;
    }
    __syncthreads();
    int i = b * 1024 + tid;
    if (i < NN) {
        int rp = g_rowptr[i] + s_off;
        g_rowptr[i] = rp;
        g_cursor[i] = rp;
    }
    if (i == 0) g_rowptr[NN] = EE;
}

// CSR scatter (by dst) fused with w[s] accumulation.
__global__ void k_scatter_wsum(const int* __restrict__ src, const int* __restrict__ dst) {
    int i = blockIdx.x * blockDim.x + threadIdx.x;
    int stride = gridDim.x * blockDim.x;
    for (int e = i; e < EE; e += stride) {
        int s = src[e];
        int d = dst[e];
        int p = atomicAdd(&g_cursor[d], 1);
        g_csr_src[p] = s;
        atomicAdd(&g_w[s], g_c_dst[d]);
    }
}

// ---------------- bf16 mma.sync split GEMM: g_h = (feat * c_src) @ W1 ----------------
// 3-term split: a = ah + al, w = wh + wl;  a@w ≈ ah@wh + ah@wl + al@wh  (~2^-16 rel err)
// smem tiles padded to 136 bf16/row (272 B) -> ldmatrix conflict-free.
#define TPAD 136
#define SM_AH 0
#define SM_AL (SM_AH + 128 * TPAD * 2)      // 34816
#define SM_WH (SM_AL + 128 * TPAD * 2)      // 69632
#define SM_WL (SM_WH + 128 * TPAD * 2)      // 104448
#define SM_GEMM_TOTAL (SM_WL + 128 * TPAD * 2)  // 139264

__global__ void __launch_bounds__(256)
k_gemm_mma(const float* __restrict__ feat, const float* __restrict__ W) {
    extern __shared__ char sm[];
    uint32_t smb = smem_u32(sm);
    int tid = threadIdx.x, lane = tid & 31, wid = tid >> 5;
    int row0 = blockIdx.x * 128;

    // ---- stage A: [128 x 128] fp32, scale by c_src, hi/lo bf16 split ----
    for (int idx = tid * 4; idx < 128 * 128; idx += 256 * 4) {
        int r = idx >> 7, c = idx & 127;
        int row = row0 + r;
        float4 v = make_float4(0.f, 0.f, 0.f, 0.f);
        float s = 0.0f;
        if (row < NN) {
            v = *(const float4*)&feat[(size_t)row * 128 + c];
            s = g_c_src[row];
        }
        float f0 = v.x * s, f1 = v.y * s, f2 = v.z * s, f3 = v.w * s;
        __nv_bfloat16 h0 = __float2bfloat16(f0), h1 = __float2bfloat16(f1);
        __nv_bfloat16 h2 = __float2bfloat16(f2), h3 = __float2bfloat16(f3);
        uint32_t boff = (uint32_t)(r * TPAD + c) * 2u;
        uint2 hh;
        hh.x = pack_bf2(__bfloat162float(h0), __bfloat162float(h1));
        hh.y = pack_bf2(__bfloat162float(h2), __bfloat162float(h3));
        uint2 ll;
        ll.x = pack_bf2(f0 - __bfloat162float(h0), f1 - __bfloat162float(h1));
        ll.y = pack_bf2(f2 - __bfloat162float(h2), f3 - __bfloat162float(h3));
        *(uint2*)(sm + SM_AH + boff) = hh;
        *(uint2*)(sm + SM_AL + boff) = ll;
    }

    // ---- stage W: natural [k][n] layout, hi/lo split ----
    for (int idx = tid; idx < 128 * 128; idx += 256) {
        int k = idx >> 7, n = idx & 127;
        float f = W[idx];
        __nv_bfloat16 bh = __float2bfloat16(f);
        float fl = f - __bfloat162float(bh);
        uint32_t boff = (uint32_t)(k * TPAD + n) * 2u;
        *(__nv_bfloat16*)(sm + SM_WH + boff) = bh;
        *(__nv_bfloat16*)(sm + SM_WL + boff) = __float2bfloat16(fl);
    }
    __syncthreads();

    // ---- compute: warp wid owns rows [wid*16, wid*16+16) ----
    float acc[16][4];
#pragma unroll
    for (int i = 0; i < 16; i++)
#pragma unroll
        for (int j = 0; j < 4; j++) acc[i][j] = 0.0f;

    int lrow = lane & 15;
    int lsel = (lane >> 4) << 3;  // 0 or 8 (bf16 elements)
    uint32_t a_base = smb + SM_AH + (uint32_t)((wid * 16 + lrow) * TPAD + lsel) * 2u;
    uint32_t w_base = smb + SM_WH + (uint32_t)(lrow * TPAD + lsel) * 2u;
    const uint32_t AL_OFF = SM_AL - SM_AH;
    const uint32_t WL_OFF = SM_WL - SM_WH;

#pragma unroll 1
    for (int ks = 0; ks < 8; ks++) {
        uint32_t aaddr = a_base + (uint32_t)ks * 32u;           // +16 bf16 cols
        uint32_t ah0, ah1, ah2, ah3, al0, al1, al2, al3;
        LDSM_X4(ah0, ah1, ah2, ah3, aaddr);
        LDSM_X4(al0, al1, al2, al3, aaddr + AL_OFF);
        uint32_t wrow = w_base + (uint32_t)ks * (16u * TPAD * 2u);
#pragma unroll
        for (int np = 0; np < 8; np++) {
            uint32_t waddr = wrow + (uint32_t)np * 32u;
            uint32_t bh0, bh1, bh2, bh3, bl0, bl1, bl2, bl3;
            LDSM_X4_T(bh0, bh1, bh2, bh3, waddr);
            LDSM_X4_T(bl0, bl1, bl2, bl3, waddr + WL_OFF);
            MMA_BF16(acc[2 * np],     ah0, ah1, ah2, ah3, bh0, bh1);
            MMA_BF16(acc[2 * np + 1], ah0, ah1, ah2, ah3, bh2, bh3);
            MMA_BF16(acc[2 * np],     ah0, ah1, ah2, ah3, bl0, bl1);
            MMA_BF16(acc[2 * np + 1], ah0, ah1, ah2, ah3, bl2, bl3);
            MMA_BF16(acc[2 * np],     al0, al1, al2, al3, bh0, bh1);
            MMA_BF16(acc[2 * np + 1], al0, al1, al2, al3, bh2, bh3);
        }
    }

    // ---- store: thread (g=lane>>2, t=lane&3): rows g / g+8, cols nt*8 + 2t ----
    int g = lane >> 2, t = lane & 3;
    int row_lo = row0 + wid * 16 + g;
    int row_hi = row_lo + 8;
#pragma unroll
    for (int nt = 0; nt < 16; nt++) {
        int col = nt * 8 + t * 2;
        if (row_lo < NN) *(float2*)&g_h[(size_t)row_lo * 128 + col] = make_float2(acc[nt][0], acc[nt][1]);
        if (row_hi < NN) *(float2*)&g_h[(size_t)row_hi * 128 + col] = make_float2(acc[nt][2], acc[nt][3]);
    }
}

// CSR aggregation of g_h + fused epilogue + fused weighted reduction into g_vacc.
__global__ void __launch_bounds__(256) k_spmm_vacc(const float* __restrict__ b1) {
    __shared__ float sv[8][HID_F];
    int tid = threadIdx.x;
    int lane = tid & 31, wid = tid >> 5;
    int gw = blockIdx.x * 8 + wid;
    bool valid = (gw < NN);

    float4 o = make_float4(0.f, 0.f, 0.f, 0.f);
    if (valid) {
        int beg = g_rowptr[gw], end = g_rowptr[gw + 1];
        float4 a0 = make_float4(0.f, 0.f, 0.f, 0.f);
        float4 a1 = make_float4(0.f, 0.f, 0.f, 0.f);
        int j = beg;
        for (; j + 1 < end; j += 2) {
            int s0 = g_csr_src[j];
            int s1 = g_csr_src[j + 1];
            float4 v0 = *(const float4*)(g_h + (size_t)s0 * 128 + lane * 4);
            float4 v1 = *(const float4*)(g_h + (size_t)s1 * 128 + lane * 4);
            a0.x += v0.x; a0.y += v0.y; a0.z += v0.z; a0.w += v0.w;
            a1.x += v1.x; a1.y += v1.y; a1.z += v1.z; a1.w += v1.w;
        }
        if (j < end) {
            int s = g_csr_src[j];
            float4 v = *(const float4*)(g_h + (size_t)s * 128 + lane * 4);
            a0.x += v.x; a0.y += v.y; a0.z += v.z; a0.w += v.w;
        }
        float cd = g_c_dst[gw], cs = g_c_src[gw];
        float wn = g_w[gw] * cs;
        float4 bb = *(const float4*)(b1 + lane * 4);
        o.x = fmaxf(fmaf(a0.x + a1.x, cd, bb.x), 0.0f) * wn;
        o.y = fmaxf(fmaf(a0.y + a1.y, cd, bb.y), 0.0f) * wn;
        o.z = fmaxf(fmaf(a0.z + a1.z, cd, bb.z), 0.0f) * wn;
        o.w = fmaxf(fmaf(a0.w + a1.w, cd, bb.w), 0.0f) * wn;
    }
    *(float4*)&sv[wid][lane * 4] = o;
    __syncthreads();
    if (tid < HID_F) {
        float s = 0.0f;
#pragma unroll
        for (int w = 0; w < 8; w++) s += sv[w][tid];
        atomicAdd(&g_vacc[tid], s);
    }
}

// out = (g_vacc @ W2) / N + b2   -> [1, 64]
__global__ void k_final(const float* __restrict__ W2, const float* __restrict__ b2,
                        float* __restrict__ out) {
    __shared__ float v[HID_F];
    int tid = threadIdx.x;
    if (tid < HID_F) v[tid] = g_vacc[tid];
    __syncthreads();
    if (tid < OUT_F) {
        float s = 0.0f;
#pragma unroll 8
        for (int k = 0; k < HID_F; k++) s = fmaf(v[k], W2[k * OUT_F + tid], s);
        out[tid] = s * (1.0f / (float)NN) + b2[tid];
    }
}

// ---------------- launch ----------------
extern "C" void kernel_launch(void* const* d_in, const int* in_sizes, int n_in,
                              void* d_out, int out_size) {
    const float* feat = (const float*)d_in[0];
    const int*   src  = (const int*)d_in[1];
    const int*   dst  = (const int*)d_in[2];
    const float* W1   = (const float*)d_in[3];
    const float* b1   = (const float*)d_in[4];
    const float* W2   = (const float*)d_in[5];
    const float* b2   = (const float*)d_in[6];
    float* out = (float*)d_out;

    (void)in_sizes; (void)n_in; (void)out_size;

    k_zero<<<256, 256>>>();
    k_degree<<<2048, 256>>>(src, dst);
    k_scan1<<<NB_SCAN, 1024>>>();
    k_scan3<<<NB_SCAN, 1024>>>();
    k_scatter_wsum<<<2048, 256>>>(src, dst);

    cudaFuncSetAttribute(k_gemm_mma, cudaFuncAttributeMaxDynamicSharedMemorySize, SM_GEMM_TOTAL);
    k_gemm_mma<<<(NN + 127) / 128, 256, SM_GEMM_TOTAL>>>(feat, W1);

    k_spmm_vacc<<<(NN + 7) / 8, 256>>>(b1);
    k_final<<<1, 128>>>(W2, b2, out);
}

// round 7
// speedup vs baseline: 2.0789x; 1.1232x over previous
#include <cuda_runtime.h>
#include <cuda_bf16.h>
#include <cstdint>

#define NN 100000
#define EE 1600000
#define HID_F 128
#define OUT_F 64
#define NB_SCAN 98   // ceil(NN/1024)

// ---------------- scratch (static device globals; no allocation) ----------------
__device__ __align__(128) int      g_outdeg[NN];
__device__ __align__(128) int      g_indeg[NN];
__device__ __align__(128) float    g_c_src[NN];
__device__ __align__(128) float    g_c_dst[NN];
__device__ __align__(128) int      g_rowptr[NN + 1];
__device__ __align__(128) int      g_cursor[NN];
__device__ __align__(128) int      g_csr_src[EE];
__device__ __align__(128) float    g_w[NN];                     // w[s] = sum_{e:src=s} c_dst[dst_e]
__device__ __align__(128) uint32_t g_hb[(size_t)NN * 64];       // layer1 out, bf16x2 packed
__device__ __align__(128) float    g_vacc[HID_F];               // sum_s w[s]*relu(...)[s]
__device__ __align__(128) int      g_bsum[NB_SCAN];

// ---------------- host-side fork/join objects (created at load, before checkpoints) ----
struct HostCtx {
    cudaStream_t s2;
    cudaEvent_t ev_fork, ev_join;
    HostCtx() {
        cudaStreamCreateWithFlags(&s2, cudaStreamNonBlocking);
        cudaEventCreateWithFlags(&ev_fork, cudaEventDisableTiming);
        cudaEventCreateWithFlags(&ev_join, cudaEventDisableTiming);
    }
};
static HostCtx g_ctx;

// ---------------- helpers ----------------
__device__ __forceinline__ uint32_t smem_u32(const void* p) {
    uint32_t a;
    asm("{ .reg .u64 t; cvta.to.shared.u64 t, %1; cvt.u32.u64 %0, t; }" : "=r"(a) : "l"(p));
    return a;
}

#define LDSM_X4(r0, r1, r2, r3, addr) \
    asm volatile("ldmatrix.sync.aligned.m8n8.x4.shared.b16 {%0,%1,%2,%3}, [%4];" \
                 : "=r"(r0), "=r"(r1), "=r"(r2), "=r"(r3) : "r"(addr))

#define LDSM_X4_T(r0, r1, r2, r3, addr) \
    asm volatile("ldmatrix.sync.aligned.m8n8.x4.trans.shared.b16 {%0,%1,%2,%3}, [%4];" \
                 : "=r"(r0), "=r"(r1), "=r"(r2), "=r"(r3) : "r"(addr))

#define MMA_BF16(d, a0, a1, a2, a3, b0, b1) \
    asm volatile("mma.sync.aligned.m16n8k16.row.col.f32.bf16.bf16.f32 " \
                 "{%0,%1,%2,%3}, {%4,%5,%6,%7}, {%8,%9}, {%0,%1,%2,%3};" \
                 : "+f"((d)[0]), "+f"((d)[1]), "+f"((d)[2]), "+f"((d)[3]) \
                 : "r"(a0), "r"(a1), "r"(a2), "r"(a3), "r"(b0), "r"(b1))

__device__ __forceinline__ uint32_t pack_bf2(float f0, float f1) {
    __nv_bfloat162 t = __floats2bfloat162_rn(f0, f1);  // .x = f0 in low 16 bits
    return *reinterpret_cast<uint32_t*>(&t);
}

// ---------------- kernels ----------------

__global__ void k_zero() {
    int i = blockIdx.x * blockDim.x + threadIdx.x;
    int stride = gridDim.x * blockDim.x;
    for (int t = i; t < NN; t += stride) {
        g_outdeg[t] = 0; g_indeg[t] = 0; g_w[t] = 0.0f;
    }
    if (i < HID_F) g_vacc[i] = 0.0f;
}

__global__ void k_degree(const int* __restrict__ src, const int* __restrict__ dst) {
    int i = blockIdx.x * blockDim.x + threadIdx.x;
    int stride = gridDim.x * blockDim.x;
    for (int e = i; e < EE; e += stride) {
        atomicAdd(&g_outdeg[src[e]], 1);
        atomicAdd(&g_indeg[dst[e]], 1);
    }
}

// Per-block exclusive scan of g_indeg (local) + block totals; fused coeff computation.
__global__ void __launch_bounds__(1024) k_scan1() {
    __shared__ int wsum[32];
    int tid = threadIdx.x;
    int lane = tid & 31, wid = tid >> 5;
    int i = blockIdx.x * 1024 + tid;
    int v = (i < NN) ? g_indeg[i] : 0;

    if (i < NN) {
        g_c_src[i] = rsqrtf((float)max(g_outdeg[i], 1));
        g_c_dst[i] = rsqrtf((float)max(v, 1));
    }

    int x = v;
#pragma unroll
    for (int off = 1; off < 32; off <<= 1) {
        int y = __shfl_up_sync(0xffffffffu, x, off);
        if (lane >= off) x += y;
    }
    if (lane == 31) wsum[wid] = x;
    __syncthreads();
    if (wid == 0) {
        int s = wsum[lane];
#pragma unroll
        for (int off = 1; off < 32; off <<= 1) {
            int y = __shfl_up_sync(0xffffffffu, s, off);
            if (lane >= off) s += y;
        }
        wsum[lane] = s;
    }
    __syncthreads();
    int excl = x - v + ((wid == 0) ? 0 : wsum[wid - 1]);
    if (i < NN) g_rowptr[i] = excl;   // local exclusive; global offset added in scan3
    if (tid == 0) g_bsum[blockIdx.x] = wsum[31];
}

// Add block offsets (each block prefix-sums the 98 block sums itself); init cursor.
__global__ void __launch_bounds__(1024) k_scan3() {
    __shared__ int s_off;
    int tid = threadIdx.x;
    int b = blockIdx.x;
    if (tid < 32) {
        int off = 0;
#pragma unroll
        for (int c = 0; c < (NB_SCAN + 31) / 32; c++) {
            int idx = c * 32 + tid;
            if (idx < b) off += g_bsum[idx];
        }
#pragma unroll
        for (int o = 16; o > 0; o >>= 1) off += __shfl_down_sync(0xffffffffu, off, o);
        if (tid == 0) s_off = off;
    }
    __syncthreads();
    int i = b * 1024 + tid;
    if (i < NN) {
        int rp = g_rowptr[i] + s_off;
        g_rowptr[i] = rp;
        g_cursor[i] = rp;
    }
    if (i == 0) g_rowptr[NN] = EE;
}

// CSR scatter (by dst) fused with w[s] accumulation.
__global__ void k_scatter_wsum(const int* __restrict__ src, const int* __restrict__ dst) {
    int i = blockIdx.x * blockDim.x + threadIdx.x;
    int stride = gridDim.x * blockDim.x;
    for (int e = i; e < EE; e += stride) {
        int s = src[e];
        int d = dst[e];
        int p = atomicAdd(&g_cursor[d], 1);
        g_csr_src[p] = s;
        atomicAdd(&g_w[s], g_c_dst[d]);
    }
}

// ---------------- bf16 mma.sync split GEMM: g_hb = bf16((feat * c_src) @ W1) ----------------
// 3-term split: a = ah + al, w = wh + wl;  a@w ≈ ah@wh + ah@wl + al@wh  (~2^-16 rel err)
// Depends only on g_outdeg (c_src computed inline) -> can overlap with scan/scatter.
#define TPAD 136
#define SM_AH 0
#define SM_AL (SM_AH + 128 * TPAD * 2)
#define SM_WH (SM_AL + 128 * TPAD * 2)
#define SM_WL (SM_WH + 128 * TPAD * 2)
#define SM_GEMM_TOTAL (SM_WL + 128 * TPAD * 2)  // 139264

__global__ void __launch_bounds__(256)
k_gemm_mma(const float* __restrict__ feat, const float* __restrict__ W) {
    extern __shared__ char sm[];
    uint32_t smb = smem_u32(sm);
    int tid = threadIdx.x, lane = tid & 31, wid = tid >> 5;
    int row0 = blockIdx.x * 128;

    // ---- stage A: [128 x 128] fp32, scale by c_src (from outdeg), hi/lo bf16 split ----
    for (int idx = tid * 4; idx < 128 * 128; idx += 256 * 4) {
        int r = idx >> 7, c = idx & 127;
        int row = row0 + r;
        float4 v = make_float4(0.f, 0.f, 0.f, 0.f);
        float s = 0.0f;
        if (row < NN) {
            v = *(const float4*)&feat[(size_t)row * 128 + c];
            s = rsqrtf((float)max(g_outdeg[row], 1));
        }
        float f0 = v.x * s, f1 = v.y * s, f2 = v.z * s, f3 = v.w * s;
        __nv_bfloat16 h0 = __float2bfloat16(f0), h1 = __float2bfloat16(f1);
        __nv_bfloat16 h2 = __float2bfloat16(f2), h3 = __float2bfloat16(f3);
        uint32_t boff = (uint32_t)(r * TPAD + c) * 2u;
        uint2 hh;
        hh.x = pack_bf2(__bfloat162float(h0), __bfloat162float(h1));
        hh.y = pack_bf2(__bfloat162float(h2), __bfloat162float(h3));
        uint2 ll;
        ll.x = pack_bf2(f0 - __bfloat162float(h0), f1 - __bfloat162float(h1));
        ll.y = pack_bf2(f2 - __bfloat162float(h2), f3 - __bfloat162float(h3));
        *(uint2*)(sm + SM_AH + boff) = hh;
        *(uint2*)(sm + SM_AL + boff) = ll;
    }

    // ---- stage W: natural [k][n] layout, hi/lo split ----
    for (int idx = tid; idx < 128 * 128; idx += 256) {
        int k = idx >> 7, n = idx & 127;
        float f = W[idx];
        __nv_bfloat16 bh = __float2bfloat16(f);
        float fl = f - __bfloat162float(bh);
        uint32_t boff = (uint32_t)(k * TPAD + n) * 2u;
        *(__nv_bfloat16*)(sm + SM_WH + boff) = bh;
        *(__nv_bfloat16*)(sm + SM_WL + boff) = __float2bfloat16(fl);
    }
    __syncthreads();

    // ---- compute: warp wid owns rows [wid*16, wid*16+16) ----
    float acc[16][4];
#pragma unroll
    for (int i = 0; i < 16; i++)
#pragma unroll
        for (int j = 0; j < 4; j++) acc[i][j] = 0.0f;

    int lrow = lane & 15;
    int lsel = (lane >> 4) << 3;
    uint32_t a_base = smb + SM_AH + (uint32_t)((wid * 16 + lrow) * TPAD + lsel) * 2u;
    uint32_t w_base = smb + SM_WH + (uint32_t)(lrow * TPAD + lsel) * 2u;
    const uint32_t AL_OFF = SM_AL - SM_AH;
    const uint32_t WL_OFF = SM_WL - SM_WH;

#pragma unroll 1
    for (int ks = 0; ks < 8; ks++) {
        uint32_t aaddr = a_base + (uint32_t)ks * 32u;
        uint32_t ah0, ah1, ah2, ah3, al0, al1, al2, al3;
        LDSM_X4(ah0, ah1, ah2, ah3, aaddr);
        LDSM_X4(al0, al1, al2, al3, aaddr + AL_OFF);
        uint32_t wrow = w_base + (uint32_t)ks * (16u * TPAD * 2u);
#pragma unroll
        for (int np = 0; np < 8; np++) {
            uint32_t waddr = wrow + (uint32_t)np * 32u;
            uint32_t bh0, bh1, bh2, bh3, bl0, bl1, bl2, bl3;
            LDSM_X4_T(bh0, bh1, bh2, bh3, waddr);
            LDSM_X4_T(bl0, bl1, bl2, bl3, waddr + WL_OFF);
            MMA_BF16(acc[2 * np],     ah0, ah1, ah2, ah3, bh0, bh1);
            MMA_BF16(acc[2 * np + 1], ah0, ah1, ah2, ah3, bh2, bh3);
            MMA_BF16(acc[2 * np],     ah0, ah1, ah2, ah3, bl0, bl1);
            MMA_BF16(acc[2 * np + 1], ah0, ah1, ah2, ah3, bl2, bl3);
            MMA_BF16(acc[2 * np],     al0, al1, al2, al3, bh0, bh1);
            MMA_BF16(acc[2 * np + 1], al0, al1, al2, al3, bh2, bh3);
        }
    }

    // ---- store bf16x2: thread (g=lane>>2, t=lane&3): rows g / g+8, u32 col idx nt*4+t ----
    int g = lane >> 2, t = lane & 3;
    int row_lo = row0 + wid * 16 + g;
    int row_hi = row_lo + 8;
#pragma unroll
    for (int nt = 0; nt < 16; nt++) {
        uint32_t plo = pack_bf2(acc[nt][0], acc[nt][1]);
        uint32_t phi = pack_bf2(acc[nt][2], acc[nt][3]);
        int ci = nt * 4 + t;
        if (row_lo < NN) g_hb[(size_t)row_lo * 64 + ci] = plo;
        if (row_hi < NN) g_hb[(size_t)row_hi * 64 + ci] = phi;
    }
}

// CSR aggregation of bf16 g_hb + fused epilogue + fused weighted reduction into g_vacc.
__global__ void __launch_bounds__(256) k_spmm_vacc(const float* __restrict__ b1) {
    __shared__ float sv[8][HID_F];
    int tid = threadIdx.x;
    int lane = tid & 31, wid = tid >> 5;
    int gw = blockIdx.x * 8 + wid;
    bool valid = (gw < NN);

    float4 o = make_float4(0.f, 0.f, 0.f, 0.f);
    if (valid) {
        int beg = g_rowptr[gw], end = g_rowptr[gw + 1];
        float4 a0 = make_float4(0.f, 0.f, 0.f, 0.f);
        float4 a1 = make_float4(0.f, 0.f, 0.f, 0.f);
        int j = beg;
        for (; j + 1 < end; j += 2) {
            int s0 = g_csr_src[j];
            int s1 = g_csr_src[j + 1];
            uint2 v0 = *(const uint2*)(g_hb + (size_t)s0 * 64 + lane * 2);
            uint2 v1 = *(const uint2*)(g_hb + (size_t)s1 * 64 + lane * 2);
            float2 f00 = __bfloat1622float2(*reinterpret_cast<__nv_bfloat162*>(&v0.x));
            float2 f01 = __bfloat1622float2(*reinterpret_cast<__nv_bfloat162*>(&v0.y));
            float2 f10 = __bfloat1622float2(*reinterpret_cast<__nv_bfloat162*>(&v1.x));
            float2 f11 = __bfloat1622float2(*reinterpret_cast<__nv_bfloat162*>(&v1.y));
            a0.x += f00.x; a0.y += f00.y; a0.z += f01.x; a0.w += f01.y;
            a1.x += f10.x; a1.y += f10.y; a1.z += f11.x; a1.w += f11.y;
        }
        if (j < end) {
            int s = g_csr_src[j];
            uint2 v = *(const uint2*)(g_hb + (size_t)s * 64 + lane * 2);
            float2 f0 = __bfloat1622float2(*reinterpret_cast<__nv_bfloat162*>(&v.x));
            float2 f1 = __bfloat1622float2(*reinterpret_cast<__nv_bfloat162*>(&v.y));
            a0.x += f0.x; a0.y += f0.y; a0.z += f1.x; a0.w += f1.y;
        }
        float cd = g_c_dst[gw], cs = g_c_src[gw];
        float wn = g_w[gw] * cs;
        float4 bb = *(const float4*)(b1 + lane * 4);
        o.x = fmaxf(fmaf(a0.x + a1.x, cd, bb.x), 0.0f) * wn;
        o.y = fmaxf(fmaf(a0.y + a1.y, cd, bb.y), 0.0f) * wn;
        o.z = fmaxf(fmaf(a0.z + a1.z, cd, bb.z), 0.0f) * wn;
        o.w = fmaxf(fmaf(a0.w + a1.w, cd, bb.w), 0.0f) * wn;
    }
    *(float4*)&sv[wid][lane * 4] = o;
    __syncthreads();
    if (tid < HID_F) {
        float s = 0.0f;
#pragma unroll
        for (int w = 0; w < 8; w++) s += sv[w][tid];
        atomicAdd(&g_vacc[tid], s);
    }
}

// out = (g_vacc @ W2) / N + b2   -> [1, 64]
__global__ void k_final(const float* __restrict__ W2, const float* __restrict__ b2,
                        float* __restrict__ out) {
    __shared__ float v[HID_F];
    int tid = threadIdx.x;
    if (tid < HID_F) v[tid] = g_vacc[tid];
    __syncthreads();
    if (tid < OUT_F) {
        float s = 0.0f;
#pragma unroll 8
        for (int k = 0; k < HID_F; k++) s = fmaf(v[k], W2[k * OUT_F + tid], s);
        out[tid] = s * (1.0f / (float)NN) + b2[tid];
    }
}

// ---------------- launch ----------------
extern "C" void kernel_launch(void* const* d_in, const int* in_sizes, int n_in,
                              void* d_out, int out_size) {
    const float* feat = (const float*)d_in[0];
    const int*   src  = (const int*)d_in[1];
    const int*   dst  = (const int*)d_in[2];
    const float* W1   = (const float*)d_in[3];
    const float* b1   = (const float*)d_in[4];
    const float* W2   = (const float*)d_in[5];
    const float* b2   = (const float*)d_in[6];
    float* out = (float*)d_out;

    (void)in_sizes; (void)n_in; (void)out_size;

    cudaFuncSetAttribute(k_gemm_mma, cudaFuncAttributeMaxDynamicSharedMemorySize, SM_GEMM_TOTAL);

    k_zero<<<256, 256>>>();
    k_degree<<<2048, 256>>>(src, dst);

    // Fork: GEMM depends only on degree(outdeg)+feat; runs parallel to scan/scatter.
    cudaEventRecord(g_ctx.ev_fork, 0);
    cudaStreamWaitEvent(g_ctx.s2, g_ctx.ev_fork, 0);
    k_gemm_mma<<<(NN + 127) / 128, 256, SM_GEMM_TOTAL, g_ctx.s2>>>(feat, W1);
    cudaEventRecord(g_ctx.ev_join, g_ctx.s2);

    k_scan1<<<NB_SCAN, 1024>>>();
    k_scan3<<<NB_SCAN, 1024>>>();
    k_scatter_wsum<<<2048, 256>>>(src, dst);

    // Join before SpMM (needs g_hb + CSR + w + coeffs).
    cudaStreamWaitEvent(0, g_ctx.ev_join, 0);
    k_spmm_vacc<<<(NN + 7) / 8, 256>>>(b1);
    k_final<<<1, 128>>>(W2, b2, out);
}

// round 8
// speedup vs baseline: 2.7052x; 1.3013x over previous
#include <cuda_runtime.h>
#include <cuda_bf16.h>
#include <cstdint>

#define NN 100000
#define EE 1600000
#define HID_F 128
#define OUT_F 64
#define NB_SCAN 98   // ceil(NN/1024)

// ---------------- scratch (static device globals; no allocation) ----------------
__device__ __align__(128) int      g_outdeg[NN];
__device__ __align__(128) int      g_indeg[NN];
__device__ __align__(128) float    g_c_src[NN];
__device__ __align__(128) float    g_c_dst[NN];
__device__ __align__(128) int      g_rowptr[NN + 1];
__device__ __align__(128) int      g_cursor[NN];
__device__ __align__(128) int      g_csr_src[EE];
__device__ __align__(128) float    g_w[NN];                     // w[s] = sum_{e:src=s} c_dst[dst_e]
__device__ __align__(128) uint32_t g_hb[(size_t)NN * 64];       // layer1 out, bf16x2 packed
__device__ __align__(128) float    g_vacc[HID_F];               // sum_s w[s]*relu(...)[s]
__device__ __align__(128) int      g_bsum[NB_SCAN];

// ---------------- host-side fork/join objects (created at load, before checkpoints) ----
struct HostCtx {
    cudaStream_t s2;
    cudaEvent_t ev_fork, ev_join;
    HostCtx() {
        cudaStreamCreateWithFlags(&s2, cudaStreamNonBlocking);
        cudaEventCreateWithFlags(&ev_fork, cudaEventDisableTiming);
        cudaEventCreateWithFlags(&ev_join, cudaEventDisableTiming);
    }
};
static HostCtx g_ctx;

// ---------------- helpers ----------------
__device__ __forceinline__ uint32_t smem_u32(const void* p) {
    uint32_t a;
    asm("{ .reg .u64 t; cvta.to.shared.u64 t, %1; cvt.u32.u64 %0, t; }" : "=r"(a) : "l"(p));
    return a;
}

#define LDSM_X4_T(r0, r1, r2, r3, addr) \
    asm volatile("ldmatrix.sync.aligned.m8n8.x4.trans.shared.b16 {%0,%1,%2,%3}, [%4];" \
                 : "=r"(r0), "=r"(r1), "=r"(r2), "=r"(r3) : "r"(addr))

#define MMA_BF16(d, a0, a1, a2, a3, b0, b1) \
    asm volatile("mma.sync.aligned.m16n8k16.row.col.f32.bf16.bf16.f32 " \
                 "{%0,%1,%2,%3}, {%4,%5,%6,%7}, {%8,%9}, {%0,%1,%2,%3};" \
                 : "+f"((d)[0]), "+f"((d)[1]), "+f"((d)[2]), "+f"((d)[3]) \
                 : "r"(a0), "r"(a1), "r"(a2), "r"(a3), "r"(b0), "r"(b1))

__device__ __forceinline__ uint32_t pack_bf2(float f0, float f1) {
    __nv_bfloat162 t = __floats2bfloat162_rn(f0, f1);  // .x = f0 in low 16 bits
    return *reinterpret_cast<uint32_t*>(&t);
}

// split float2 -> (hi bf16x2, lo bf16x2)
__device__ __forceinline__ void split_bf2(float2 f, uint32_t& hi, uint32_t& lo) {
    __nv_bfloat16 h0 = __float2bfloat16(f.x), h1 = __float2bfloat16(f.y);
    hi = pack_bf2(__bfloat162float(h0), __bfloat162float(h1));
    lo = pack_bf2(f.x - __bfloat162float(h0), f.y - __bfloat162float(h1));
}

// ---------------- kernels ----------------

__global__ void k_zero() {
    int i = blockIdx.x * blockDim.x + threadIdx.x;
    int stride = gridDim.x * blockDim.x;
    for (int t = i; t < NN; t += stride) {
        g_outdeg[t] = 0; g_indeg[t] = 0; g_w[t] = 0.0f;
    }
    if (i < HID_F) g_vacc[i] = 0.0f;
}

__global__ void k_degree(const int* __restrict__ src, const int* __restrict__ dst) {
    int i = blockIdx.x * blockDim.x + threadIdx.x;
    int stride = gridDim.x * blockDim.x;
    for (int e = i; e < EE; e += stride) {
        atomicAdd(&g_outdeg[src[e]], 1);
        atomicAdd(&g_indeg[dst[e]], 1);
    }
}

// Per-block exclusive scan of g_indeg (local) + block totals; fused coeff computation.
__global__ void __launch_bounds__(1024) k_scan1() {
    __shared__ int wsum[32];
    int tid = threadIdx.x;
    int lane = tid & 31, wid = tid >> 5;
    int i = blockIdx.x * 1024 + tid;
    int v = (i < NN) ? g_indeg[i] : 0;

    if (i < NN) {
        g_c_src[i] = rsqrtf((float)max(g_outdeg[i], 1));
        g_c_dst[i] = rsqrtf((float)max(v, 1));
    }

    int x = v;
#pragma unroll
    for (int off = 1; off < 32; off <<= 1) {
        int y = __shfl_up_sync(0xffffffffu, x, off);
        if (lane >= off) x += y;
    }
    if (lane == 31) wsum[wid] = x;
    __syncthreads();
    if (wid == 0) {
        int s = wsum[lane];
#pragma unroll
        for (int off = 1; off < 32; off <<= 1) {
            int y = __shfl_up_sync(0xffffffffu, s, off);
            if (lane >= off) s += y;
        }
        wsum[lane] = s;
    }
    __syncthreads();
    int excl = x - v + ((wid == 0) ? 0 : wsum[wid - 1]);
    if (i < NN) g_rowptr[i] = excl;   // local exclusive; global offset added in scan3
    if (tid == 0) g_bsum[blockIdx.x] = wsum[31];
}

// Add block offsets (each block prefix-sums the 98 block sums itself); init cursor.
__global__ void __launch_bounds__(1024) k_scan3() {
    __shared__ int s_off;
    int tid = threadIdx.x;
    int b = blockIdx.x;
    if (tid < 32) {
        int off = 0;
#pragma unroll
        for (int c = 0; c < (NB_SCAN + 31) / 32; c++) {
            int idx = c * 32 + tid;
            if (idx < b) off += g_bsum[idx];
        }
#pragma unroll
        for (int o = 16; o > 0; o >>= 1) off += __shfl_down_sync(0xffffffffu, off, o);
        if (tid == 0) s_off = off;
    }
    __syncthreads();
    int i = b * 1024 + tid;
    if (i < NN) {
        int rp = g_rowptr[i] + s_off;
        g_rowptr[i] = rp;
        g_cursor[i] = rp;
    }
    if (i == 0) g_rowptr[NN] = EE;
}

// CSR scatter (by dst) fused with w[s] accumulation.
__global__ void k_scatter_wsum(const int* __restrict__ src, const int* __restrict__ dst) {
    int i = blockIdx.x * blockDim.x + threadIdx.x;
    int stride = gridDim.x * blockDim.x;
    for (int e = i; e < EE; e += stride) {
        int s = src[e];
        int d = dst[e];
        int p = atomicAdd(&g_cursor[d], 1);
        g_csr_src[p] = s;
        atomicAdd(&g_w[s], g_c_dst[d]);
    }
}

// ---------------- bf16 mma.sync split GEMM: g_hb = bf16((feat * c_src) @ W1) ----------------
// 3-term split: a = ah + al, w = wh + wl;  a@w ≈ ah@wh + ah@wl + al@wh  (~2^-16 rel err)
// A fragments loaded straight from gmem per-thread (mma layout is addressable);
// only W (hi/lo) staged in smem -> 70KB -> 2 CTAs/SM.
#define TPAD 136
#define SM_WH 0
#define SM_WL (SM_WH + 128 * TPAD * 2)
#define SM_GEMM_TOTAL (SM_WL + 128 * TPAD * 2)  // 69632

__global__ void __launch_bounds__(256, 2)
k_gemm_mma(const float* __restrict__ feat, const float* __restrict__ W) {
    extern __shared__ char sm[];
    uint32_t smb = smem_u32(sm);
    int tid = threadIdx.x, lane = tid & 31, wid = tid >> 5;
    int row0 = blockIdx.x * 128;

    // ---- stage W: natural [k][n] layout, hi/lo split ----
    for (int idx = tid; idx < 128 * 128; idx += 256) {
        int k = idx >> 7, n = idx & 127;
        float f = W[idx];
        __nv_bfloat16 bh = __float2bfloat16(f);
        float fl = f - __bfloat162float(bh);
        uint32_t boff = (uint32_t)(k * TPAD + n) * 2u;
        *(__nv_bfloat16*)(sm + SM_WH + boff) = bh;
        *(__nv_bfloat16*)(sm + SM_WL + boff) = __float2bfloat16(fl);
    }
    __syncthreads();

    // ---- per-thread A addressing (mma m16n8k16 fragment layout) ----
    int g = lane >> 2, t = lane & 3;
    int rowA = row0 + wid * 16 + g;    // rows g and g+8 of this warp's 16-row tile
    int rowB = rowA + 8;
    bool vA = rowA < NN, vB = rowB < NN;
    float sA = vA ? rsqrtf((float)max(g_outdeg[rowA], 1)) : 0.0f;
    float sB = vB ? rsqrtf((float)max(g_outdeg[rowB], 1)) : 0.0f;
    const float2* pA = (const float2*)(feat + (size_t)(vA ? rowA : 0) * 128);
    const float2* pB = (const float2*)(feat + (size_t)(vB ? rowB : 0) * 128);

    float acc[16][4];
#pragma unroll
    for (int i = 0; i < 16; i++)
#pragma unroll
        for (int j = 0; j < 4; j++) acc[i][j] = 0.0f;

    int lrow = lane & 15;
    int lsel = (lane >> 4) << 3;
    uint32_t w_base = smb + SM_WH + (uint32_t)(lrow * TPAD + lsel) * 2u;
    const uint32_t WL_OFF = SM_WL - SM_WH;

#pragma unroll 1
    for (int ks = 0; ks < 8; ks++) {
        // A fragment: cols k0+2t (frag 0/1) and k0+8+2t (frag 2/3), k0 = 16*ks
        int c0 = ks * 8 + t;       // float2 index of col k0+2t
        int c1 = c0 + 4;           // +8 cols
        float2 f0 = pA[c0], f1 = pB[c0], f2 = pA[c1], f3 = pB[c1];
        f0.x *= sA; f0.y *= sA; f2.x *= sA; f2.y *= sA;
        f1.x *= sB; f1.y *= sB; f3.x *= sB; f3.y *= sB;
        uint32_t ah0, ah1, ah2, ah3, al0, al1, al2, al3;
        split_bf2(f0, ah0, al0);
        split_bf2(f1, ah1, al1);
        split_bf2(f2, ah2, al2);
        split_bf2(f3, ah3, al3);

        uint32_t wrow = w_base + (uint32_t)ks * (16u * TPAD * 2u);
#pragma unroll
        for (int np = 0; np < 8; np++) {
            uint32_t waddr = wrow + (uint32_t)np * 32u;
            uint32_t bh0, bh1, bh2, bh3, bl0, bl1, bl2, bl3;
            LDSM_X4_T(bh0, bh1, bh2, bh3, waddr);
            LDSM_X4_T(bl0, bl1, bl2, bl3, waddr + WL_OFF);
            MMA_BF16(acc[2 * np],     ah0, ah1, ah2, ah3, bh0, bh1);
            MMA_BF16(acc[2 * np + 1], ah0, ah1, ah2, ah3, bh2, bh3);
            MMA_BF16(acc[2 * np],     ah0, ah1, ah2, ah3, bl0, bl1);
            MMA_BF16(acc[2 * np + 1], ah0, ah1, ah2, ah3, bl2, bl3);
            MMA_BF16(acc[2 * np],     al0, al1, al2, al3, bh0, bh1);
            MMA_BF16(acc[2 * np + 1], al0, al1, al2, al3, bh2, bh3);
        }
    }

    // ---- store bf16x2: rows g / g+8, u32 col idx nt*4+t ----
#pragma unroll
    for (int nt = 0; nt < 16; nt++) {
        uint32_t plo = pack_bf2(acc[nt][0], acc[nt][1]);
        uint32_t phi = pack_bf2(acc[nt][2], acc[nt][3]);
        int ci = nt * 4 + t;
        if (vA) g_hb[(size_t)rowA * 64 + ci] = plo;
        if (vB) g_hb[(size_t)rowB * 64 + ci] = phi;
    }
}

// CSR aggregation of bf16 g_hb + fused epilogue + fused weighted reduction into g_vacc.
__global__ void __launch_bounds__(256) k_spmm_vacc(const float* __restrict__ b1) {
    __shared__ float sv[8][HID_F];
    int tid = threadIdx.x;
    int lane = tid & 31, wid = tid >> 5;
    int gw = blockIdx.x * 8 + wid;
    bool valid = (gw < NN);

    float4 o = make_float4(0.f, 0.f, 0.f, 0.f);
    if (valid) {
        int beg = g_rowptr[gw], end = g_rowptr[gw + 1];
        float4 a0 = make_float4(0.f, 0.f, 0.f, 0.f);
        float4 a1 = make_float4(0.f, 0.f, 0.f, 0.f);
        int j = beg;
        // 4-deep unroll: 4 independent 256B row gathers in flight
        for (; j + 3 < end; j += 4) {
            int s0 = g_csr_src[j], s1 = g_csr_src[j + 1];
            int s2 = g_csr_src[j + 2], s3 = g_csr_src[j + 3];
            uint2 v0 = *(const uint2*)(g_hb + (size_t)s0 * 64 + lane * 2);
            uint2 v1 = *(const uint2*)(g_hb + (size_t)s1 * 64 + lane * 2);
            uint2 v2 = *(const uint2*)(g_hb + (size_t)s2 * 64 + lane * 2);
            uint2 v3 = *(const uint2*)(g_hb + (size_t)s3 * 64 + lane * 2);
            float2 f00 = __bfloat1622float2(*reinterpret_cast<__nv_bfloat162*>(&v0.x));
            float2 f01 = __bfloat1622float2(*reinterpret_cast<__nv_bfloat162*>(&v0.y));
            float2 f10 = __bfloat1622float2(*reinterpret_cast<__nv_bfloat162*>(&v1.x));
            float2 f11 = __bfloat1622float2(*reinterpret_cast<__nv_bfloat162*>(&v1.y));
            float2 f20 = __bfloat1622float2(*reinterpret_cast<__nv_bfloat162*>(&v2.x));
            float2 f21 = __bfloat1622float2(*reinterpret_cast<__nv_bfloat162*>(&v2.y));
            float2 f30 = __bfloat1622float2(*reinterpret_cast<__nv_bfloat162*>(&v3.x));
            float2 f31 = __bfloat1622float2(*reinterpret_cast<__nv_bfloat162*>(&v3.y));
            a0.x += f00.x + f20.x; a0.y += f00.y + f20.y;
            a0.z += f01.x + f21.x; a0.w += f01.y + f21.y;
            a1.x += f10.x + f30.x; a1.y += f10.y + f30.y;
            a1.z += f11.x + f31.x; a1.w += f11.y + f31.y;
        }
        for (; j < end; j++) {
            int s = g_csr_src[j];
            uint2 v = *(const uint2*)(g_hb + (size_t)s * 64 + lane * 2);
            float2 f0 = __bfloat1622float2(*reinterpret_cast<__nv_bfloat162*>(&v.x));
            float2 f1 = __bfloat1622float2(*reinterpret_cast<__nv_bfloat162*>(&v.y));
            a0.x += f0.x; a0.y += f0.y; a0.z += f1.x; a0.w += f1.y;
        }
        float cd = g_c_dst[gw], cs = g_c_src[gw];
        float wn = g_w[gw] * cs;
        float4 bb = *(const float4*)(b1 + lane * 4);
        o.x = fmaxf(fmaf(a0.x + a1.x, cd, bb.x), 0.0f) * wn;
        o.y = fmaxf(fmaf(a0.y + a1.y, cd, bb.y), 0.0f) * wn;
        o.z = fmaxf(fmaf(a0.z + a1.z, cd, bb.z), 0.0f) * wn;
        o.w = fmaxf(fmaf(a0.w + a1.w, cd, bb.w), 0.0f) * wn;
    }
    *(float4*)&sv[wid][lane * 4] = o;
    __syncthreads();
    if (tid < HID_F) {
        float s = 0.0f;
#pragma unroll
        for (int w = 0; w < 8; w++) s += sv[w][tid];
        atomicAdd(&g_vacc[tid], s);
    }
}

// out = (g_vacc @ W2) / N + b2   -> [1, 64]
__global__ void k_final(const float* __restrict__ W2, const float* __restrict__ b2,
                        float* __restrict__ out) {
    __shared__ float v[HID_F];
    int tid = threadIdx.x;
    if (tid < HID_F) v[tid] = g_vacc[tid];
    __syncthreads();
    if (tid < OUT_F) {
        float s = 0.0f;
#pragma unroll 8
        for (int k = 0; k < HID_F; k++) s = fmaf(v[k], W2[k * OUT_F + tid], s);
        out[tid] = s * (1.0f / (float)NN) + b2[tid];
    }
}

// ---------------- launch ----------------
extern "C" void kernel_launch(void* const* d_in, const int* in_sizes, int n_in,
                              void* d_out, int out_size) {
    const float* feat = (const float*)d_in[0];
    const int*   src  = (const int*)d_in[1];
    const int*   dst  = (const int*)d_in[2];
    const float* W1   = (const float*)d_in[3];
    const float* b1   = (const float*)d_in[4];
    const float* W2   = (const float*)d_in[5];
    const float* b2   = (const float*)d_in[6];
    float* out = (float*)d_out;

    (void)in_sizes; (void)n_in; (void)out_size;

    cudaFuncSetAttribute(k_gemm_mma, cudaFuncAttributeMaxDynamicSharedMemorySize, SM_GEMM_TOTAL);

    k_zero<<<256, 256>>>();
    k_degree<<<2048, 256>>>(src, dst);

    // Fork: GEMM depends only on degree(outdeg)+feat; runs parallel to scan/scatter.
    cudaEventRecord(g_ctx.ev_fork, 0);
    cudaStreamWaitEvent(g_ctx.s2, g_ctx.ev_fork, 0);
    k_gemm_mma<<<(NN + 127) / 128, 256, SM_GEMM_TOTAL, g_ctx.s2>>>(feat, W1);
    cudaEventRecord(g_ctx.ev_join, g_ctx.s2);

    k_scan1<<<NB_SCAN, 1024>>>();
    k_scan3<<<NB_SCAN, 1024>>>();
    k_scatter_wsum<<<2048, 256>>>(src, dst);

    // Join before SpMM (needs g_hb + CSR + w + coeffs).
    cudaStreamWaitEvent(0, g_ctx.ev_join, 0);
    k_spmm_vacc<<<(NN + 7) / 8, 256>>>(b1);
    k_final<<<1, 128>>>(W2, b2, out);
}

// round 9
// speedup vs baseline: 2.7738x; 1.0254x over previous
#include <cuda_runtime.h>
#include <cuda_bf16.h>
#include <cuda_fp8.h>
#include <cstdint>

#define NN 100000
#define EE 1600000
#define HID_F 128
#define OUT_F 64
#define NB_SCAN 98   // ceil(NN/1024)

// ---------------- scratch (static device globals; no allocation) ----------------
__device__ __align__(128) int      g_outdeg[NN];
__device__ __align__(128) int      g_indeg[NN];
__device__ __align__(128) float    g_c_dst[NN];
__device__ __align__(128) int      g_rowptr[NN + 1];
__device__ __align__(128) int      g_cursor[NN];
__device__ __align__(128) int      g_csr_src[EE];
__device__ __align__(128) float    g_w[NN];                    // w[s] = sum_{e:src=s} c_dst[dst_e]
__device__ __align__(128) uint8_t  g_h8[(size_t)NN * HID_F];   // layer1 out, fp8 e4m3
__device__ __align__(128) float    g_vacc[HID_F];              // sum_s w[s]*relu(...)[s]
__device__ __align__(128) int      g_bsum[NB_SCAN];

// ---------------- host-side fork/join objects (created at load, before checkpoints) ----
struct HostCtx {
    cudaStream_t s2;
    cudaEvent_t ev_fork, ev_join;
    HostCtx() {
        cudaStreamCreateWithFlags(&s2, cudaStreamNonBlocking);
        cudaEventCreateWithFlags(&ev_fork, cudaEventDisableTiming);
        cudaEventCreateWithFlags(&ev_join, cudaEventDisableTiming);
    }
};
static HostCtx g_ctx;

// ---------------- helpers ----------------
__device__ __forceinline__ uint32_t smem_u32(const void* p) {
    uint32_t a;
    asm("{ .reg .u64 t; cvta.to.shared.u64 t, %1; cvt.u32.u64 %0, t; }" : "=r"(a) : "l"(p));
    return a;
}

#define LDSM_X4_T(r0, r1, r2, r3, addr) \
    asm volatile("ldmatrix.sync.aligned.m8n8.x4.trans.shared.b16 {%0,%1,%2,%3}, [%4];" \
                 : "=r"(r0), "=r"(r1), "=r"(r2), "=r"(r3) : "r"(addr))

#define MMA_BF16(d, a0, a1, a2, a3, b0, b1) \
    asm volatile("mma.sync.aligned.m16n8k16.row.col.f32.bf16.bf16.f32 " \
                 "{%0,%1,%2,%3}, {%4,%5,%6,%7}, {%8,%9}, {%0,%1,%2,%3};" \
                 : "+f"((d)[0]), "+f"((d)[1]), "+f"((d)[2]), "+f"((d)[3]) \
                 : "r"(a0), "r"(a1), "r"(a2), "r"(a3), "r"(b0), "r"(b1))

__device__ __forceinline__ uint32_t pack_bf2(float f0, float f1) {
    __nv_bfloat162 t = __floats2bfloat162_rn(f0, f1);
    return *reinterpret_cast<uint32_t*>(&t);
}

__device__ __forceinline__ void split_bf2(float2 f, uint32_t& hi, uint32_t& lo) {
    __nv_bfloat16 h0 = __float2bfloat16(f.x), h1 = __float2bfloat16(f.y);
    hi = pack_bf2(__bfloat162float(h0), __bfloat162float(h1));
    lo = pack_bf2(f.x - __bfloat162float(h0), f.y - __bfloat162float(h1));
}

__device__ __forceinline__ unsigned short pack_fp8x2(float a, float b) {
    float2 f = make_float2(a, b);
    return (unsigned short)__nv_cvt_float2_to_fp8x2(f, __NV_SATFINITE, __NV_E4M3);
}

__device__ __forceinline__ float2 fp8x2_f2(unsigned short u) {
    __half2_raw hr = __nv_cvt_fp8x2_to_halfraw2((__nv_fp8x2_storage_t)u, __NV_E4M3);
    return __half22float2(*reinterpret_cast<__half2*>(&hr));
}

// ---------------- kernels ----------------

__global__ void k_zero() {
    int i = blockIdx.x * blockDim.x + threadIdx.x;
    int stride = gridDim.x * blockDim.x;
    for (int t = i; t < NN; t += stride) {
        g_outdeg[t] = 0; g_indeg[t] = 0; g_w[t] = 0.0f;
    }
    if (i < HID_F) g_vacc[i] = 0.0f;
}

// out-degree only (stream 2, feeds GEMM)
__global__ void k_deg_out(const int* __restrict__ src) {
    int i = blockIdx.x * blockDim.x + threadIdx.x;
    int stride = gridDim.x * blockDim.x;
    for (int e = i; e < EE; e += stride) atomicAdd(&g_outdeg[src[e]], 1);
}

// in-degree only (stream 1, feeds scan/CSR)
__global__ void k_deg_in(const int* __restrict__ dst) {
    int i = blockIdx.x * blockDim.x + threadIdx.x;
    int stride = gridDim.x * blockDim.x;
    for (int e = i; e < EE; e += stride) atomicAdd(&g_indeg[dst[e]], 1);
}

// Per-block exclusive scan of g_indeg (local) + block totals; fused c_dst computation.
__global__ void __launch_bounds__(1024) k_scan1() {
    __shared__ int wsum[32];
    int tid = threadIdx.x;
    int lane = tid & 31, wid = tid >> 5;
    int i = blockIdx.x * 1024 + tid;
    int v = (i < NN) ? g_indeg[i] : 0;

    if (i < NN) g_c_dst[i] = rsqrtf((float)max(v, 1));

    int x = v;
#pragma unroll
    for (int off = 1; off < 32; off <<= 1) {
        int y = __shfl_up_sync(0xffffffffu, x, off);
        if (lane >= off) x += y;
    }
    if (lane == 31) wsum[wid] = x;
    __syncthreads();
    if (wid == 0) {
        int s = wsum[lane];
#pragma unroll
        for (int off = 1; off < 32; off <<= 1) {
            int y = __shfl_up_sync(0xffffffffu, s, off);
            if (lane >= off) s += y;
        }
        wsum[lane] = s;
    }
    __syncthreads();
    int excl = x - v + ((wid == 0) ? 0 : wsum[wid - 1]);
    if (i < NN) g_rowptr[i] = excl;
    if (tid == 0) g_bsum[blockIdx.x] = wsum[31];
}

// Add block offsets; init cursor; rowptr[NN] = EE.
__global__ void __launch_bounds__(1024) k_scan3() {
    __shared__ int s_off;
    int tid = threadIdx.x;
    int b = blockIdx.x;
    if (tid < 32) {
        int off = 0;
#pragma unroll
        for (int c = 0; c < (NB_SCAN + 31) / 32; c++) {
            int idx = c * 32 + tid;
            if (idx < b) off += g_bsum[idx];
        }
#pragma unroll
        for (int o = 16; o > 0; o >>= 1) off += __shfl_down_sync(0xffffffffu, off, o);
        if (tid == 0) s_off = off;
    }
    __syncthreads();
    int i = b * 1024 + tid;
    if (i < NN) {
        int rp = g_rowptr[i] + s_off;
        g_rowptr[i] = rp;
        g_cursor[i] = rp;
    }
    if (i == 0) g_rowptr[NN] = EE;
}

// CSR scatter (by dst) fused with w[s] accumulation.
__global__ void k_scatter_wsum(const int* __restrict__ src, const int* __restrict__ dst) {
    int i = blockIdx.x * blockDim.x + threadIdx.x;
    int stride = gridDim.x * blockDim.x;
    for (int e = i; e < EE; e += stride) {
        int s = src[e];
        int d = dst[e];
        int p = atomicAdd(&g_cursor[d], 1);
        g_csr_src[p] = s;
        atomicAdd(&g_w[s], g_c_dst[d]);
    }
}

// ---------------- bf16 mma.sync split GEMM: g_h8 = fp8((feat * c_src) @ W1) ----------------
#define TPAD 136
#define SM_WH 0
#define SM_WL (SM_WH + 128 * TPAD * 2)
#define SM_GEMM_TOTAL (SM_WL + 128 * TPAD * 2)  // 69632

__global__ void __launch_bounds__(256, 2)
k_gemm_mma(const float* __restrict__ feat, const float* __restrict__ W) {
    extern __shared__ char sm[];
    uint32_t smb = smem_u32(sm);
    int tid = threadIdx.x, lane = tid & 31, wid = tid >> 5;
    int row0 = blockIdx.x * 128;

    // stage W: natural [k][n] layout, hi/lo split
    for (int idx = tid; idx < 128 * 128; idx += 256) {
        int k = idx >> 7, n = idx & 127;
        float f = W[idx];
        __nv_bfloat16 bh = __float2bfloat16(f);
        float fl = f - __bfloat162float(bh);
        uint32_t boff = (uint32_t)(k * TPAD + n) * 2u;
        *(__nv_bfloat16*)(sm + SM_WH + boff) = bh;
        *(__nv_bfloat16*)(sm + SM_WL + boff) = __float2bfloat16(fl);
    }
    __syncthreads();

    int g = lane >> 2, t = lane & 3;
    int rowA = row0 + wid * 16 + g;
    int rowB = rowA + 8;
    bool vA = rowA < NN, vB = rowB < NN;
    float sA = vA ? rsqrtf((float)max(g_outdeg[rowA], 1)) : 0.0f;
    float sB = vB ? rsqrtf((float)max(g_outdeg[rowB], 1)) : 0.0f;
    const float2* pA = (const float2*)(feat + (size_t)(vA ? rowA : 0) * 128);
    const float2* pB = (const float2*)(feat + (size_t)(vB ? rowB : 0) * 128);

    float acc[16][4];
#pragma unroll
    for (int i = 0; i < 16; i++)
#pragma unroll
        for (int j = 0; j < 4; j++) acc[i][j] = 0.0f;

    int lrow = lane & 15;
    int lsel = (lane >> 4) << 3;
    uint32_t w_base = smb + SM_WH + (uint32_t)(lrow * TPAD + lsel) * 2u;
    const uint32_t WL_OFF = SM_WL - SM_WH;

#pragma unroll 1
    for (int ks = 0; ks < 8; ks++) {
        int c0 = ks * 8 + t;
        int c1 = c0 + 4;
        float2 f0 = pA[c0], f1 = pB[c0], f2 = pA[c1], f3 = pB[c1];
        f0.x *= sA; f0.y *= sA; f2.x *= sA; f2.y *= sA;
        f1.x *= sB; f1.y *= sB; f3.x *= sB; f3.y *= sB;
        uint32_t ah0, ah1, ah2, ah3, al0, al1, al2, al3;
        split_bf2(f0, ah0, al0);
        split_bf2(f1, ah1, al1);
        split_bf2(f2, ah2, al2);
        split_bf2(f3, ah3, al3);

        uint32_t wrow = w_base + (uint32_t)ks * (16u * TPAD * 2u);
#pragma unroll
        for (int np = 0; np < 8; np++) {
            uint32_t waddr = wrow + (uint32_t)np * 32u;
            uint32_t bh0, bh1, bh2, bh3, bl0, bl1, bl2, bl3;
            LDSM_X4_T(bh0, bh1, bh2, bh3, waddr);
            LDSM_X4_T(bl0, bl1, bl2, bl3, waddr + WL_OFF);
            MMA_BF16(acc[2 * np],     ah0, ah1, ah2, ah3, bh0, bh1);
            MMA_BF16(acc[2 * np + 1], ah0, ah1, ah2, ah3, bh2, bh3);
            MMA_BF16(acc[2 * np],     ah0, ah1, ah2, ah3, bl0, bl1);
            MMA_BF16(acc[2 * np + 1], ah0, ah1, ah2, ah3, bl2, bl3);
            MMA_BF16(acc[2 * np],     al0, al1, al2, al3, bh0, bh1);
            MMA_BF16(acc[2 * np + 1], al0, al1, al2, al3, bh2, bh3);
        }
    }

    // store fp8x2: rows g / g+8, byte col = nt*8 + 2t
#pragma unroll
    for (int nt = 0; nt < 16; nt++) {
        unsigned short plo = pack_fp8x2(acc[nt][0], acc[nt][1]);
        unsigned short phi = pack_fp8x2(acc[nt][2], acc[nt][3]);
        int cb = nt * 8 + t * 2;
        if (vA) *(unsigned short*)(g_h8 + (size_t)rowA * 128 + cb) = plo;
        if (vB) *(unsigned short*)(g_h8 + (size_t)rowB * 128 + cb) = phi;
    }
}

// CSR aggregation of fp8 g_h8 + fused epilogue + fused weighted reduction into g_vacc.
__global__ void __launch_bounds__(256) k_spmm_vacc(const float* __restrict__ b1) {
    __shared__ float sv[8][HID_F];
    int tid = threadIdx.x;
    int lane = tid & 31, wid = tid >> 5;
    int gw = blockIdx.x * 8 + wid;
    bool valid = (gw < NN);

    float4 o = make_float4(0.f, 0.f, 0.f, 0.f);
    if (valid) {
        int beg = g_rowptr[gw], end = g_rowptr[gw + 1];
        float4 a0 = make_float4(0.f, 0.f, 0.f, 0.f);
        float4 a1 = make_float4(0.f, 0.f, 0.f, 0.f);
        int j = beg;
        // 4-deep unroll: 4 independent 128B row gathers in flight
        for (; j + 3 < end; j += 4) {
            int s0 = g_csr_src[j], s1 = g_csr_src[j + 1];
            int s2 = g_csr_src[j + 2], s3 = g_csr_src[j + 3];
            uint32_t v0 = *(const uint32_t*)(g_h8 + (size_t)s0 * 128 + lane * 4);
            uint32_t v1 = *(const uint32_t*)(g_h8 + (size_t)s1 * 128 + lane * 4);
            uint32_t v2 = *(const uint32_t*)(g_h8 + (size_t)s2 * 128 + lane * 4);
            uint32_t v3 = *(const uint32_t*)(g_h8 + (size_t)s3 * 128 + lane * 4);
            float2 f00 = fp8x2_f2((unsigned short)(v0 & 0xFFFF));
            float2 f01 = fp8x2_f2((unsigned short)(v0 >> 16));
            float2 f10 = fp8x2_f2((unsigned short)(v1 & 0xFFFF));
            float2 f11 = fp8x2_f2((unsigned short)(v1 >> 16));
            float2 f20 = fp8x2_f2((unsigned short)(v2 & 0xFFFF));
            float2 f21 = fp8x2_f2((unsigned short)(v2 >> 16));
            float2 f30 = fp8x2_f2((unsigned short)(v3 & 0xFFFF));
            float2 f31 = fp8x2_f2((unsigned short)(v3 >> 16));
            a0.x += f00.x + f20.x; a0.y += f00.y + f20.y;
            a0.z += f01.x + f21.x; a0.w += f01.y + f21.y;
            a1.x += f10.x + f30.x; a1.y += f10.y + f30.y;
            a1.z += f11.x + f31.x; a1.w += f11.y + f31.y;
        }
        for (; j < end; j++) {
            int s = g_csr_src[j];
            uint32_t v = *(const uint32_t*)(g_h8 + (size_t)s * 128 + lane * 4);
            float2 f0 = fp8x2_f2((unsigned short)(v & 0xFFFF));
            float2 f1 = fp8x2_f2((unsigned short)(v >> 16));
            a0.x += f0.x; a0.y += f0.y; a0.z += f1.x; a0.w += f1.y;
        }
        float cd = g_c_dst[gw];
        float cs = rsqrtf((float)max(g_outdeg[gw], 1));
        float wn = g_w[gw] * cs;
        float4 bb = *(const float4*)(b1 + lane * 4);
        o.x = fmaxf(fmaf(a0.x + a1.x, cd, bb.x), 0.0f) * wn;
        o.y = fmaxf(fmaf(a0.y + a1.y, cd, bb.y), 0.0f) * wn;
        o.z = fmaxf(fmaf(a0.z + a1.z, cd, bb.z), 0.0f) * wn;
        o.w = fmaxf(fmaf(a0.w + a1.w, cd, bb.w), 0.0f) * wn;
    }
    *(float4*)&sv[wid][lane * 4] = o;
    __syncthreads();
    if (tid < HID_F) {
        float s = 0.0f;
#pragma unroll
        for (int w = 0; w < 8; w++) s += sv[w][tid];
        atomicAdd(&g_vacc[tid], s);
    }
}

// out = (g_vacc @ W2) / N + b2   -> [1, 64]
__global__ void k_final(const float* __restrict__ W2, const float* __restrict__ b2,
                        float* __restrict__ out) {
    __shared__ float v[HID_F];
    int tid = threadIdx.x;
    if (tid < HID_F) v[tid] = g_vacc[tid];
    __syncthreads();
    if (tid < OUT_F) {
        float s = 0.0f;
#pragma unroll 8
        for (int k = 0; k < HID_F; k++) s = fmaf(v[k], W2[k * OUT_F + tid], s);
        out[tid] = s * (1.0f / (float)NN) + b2[tid];
    }
}

// ---------------- launch ----------------
extern "C" void kernel_launch(void* const* d_in, const int* in_sizes, int n_in,
                              void* d_out, int out_size) {
    const float* feat = (const float*)d_in[0];
    const int*   src  = (const int*)d_in[1];
    const int*   dst  = (const int*)d_in[2];
    const float* W1   = (const float*)d_in[3];
    const float* b1   = (const float*)d_in[4];
    const float* W2   = (const float*)d_in[5];
    const float* b2   = (const float*)d_in[6];
    float* out = (float*)d_out;

    (void)in_sizes; (void)n_in; (void)out_size;

    cudaFuncSetAttribute(k_gemm_mma, cudaFuncAttributeMaxDynamicSharedMemorySize, SM_GEMM_TOTAL);

    k_zero<<<256, 256>>>();

    // Fork after zero: branch A (s2) = outdeg -> GEMM ; branch B (default) = indeg -> CSR.
    cudaEventRecord(g_ctx.ev_fork, 0);
    cudaStreamWaitEvent(g_ctx.s2, g_ctx.ev_fork, 0);
    k_deg_out<<<2048, 256, 0, g_ctx.s2>>>(src);
    k_gemm_mma<<<(NN + 127) / 128, 256, SM_GEMM_TOTAL, g_ctx.s2>>>(feat, W1);
    cudaEventRecord(g_ctx.ev_join, g_ctx.s2);

    k_deg_in<<<2048, 256>>>(dst);
    k_scan1<<<NB_SCAN, 1024>>>();
    k_scan3<<<NB_SCAN, 1024>>>();
    k_scatter_wsum<<<2048, 256>>>(src, dst);

    // Join before SpMM (needs g_h8 + outdeg from s2, CSR/w/c_dst from default).
    cudaStreamWaitEvent(0, g_ctx.ev_join, 0);
    k_spmm_vacc<<<(NN + 7) / 8, 256>>>(b1);
    k_final<<<1, 128>>>(W2, b2, out);
}